// round 2
// baseline (speedup 1.0000x reference)
#include <cuda_runtime.h>
#include <math.h>

typedef unsigned long long ull;

#define NB 2
#define NT 1024
#define DMODEL 1024
#define NH 16
#define HD 64
#define NL 12
#define NM (NB*NT)        /* 2048 rows of x */
#define NHL (NH*NL)       /* 192  */
#define NHD (NH*HD)       /* 1024 */

/* ---------------- scratch (no allocations allowed) ---------------- */
__device__ float g_Qp[NB*NH*NT*HD];     /* [B,H,T,D] phi(Q) */
__device__ float g_Kp[NB*NH*NT*HD];     /* [B,H,T,D] phi(K) */
__device__ float g_V [NB*NH*NT*HD];     /* [B,H,T,D]        */
__device__ float g_logits[NM*NHL];      /* [M, H*L]         */
__device__ float g_w[NB*NH*NT*NL];      /* [B,H,T,L] softmax */
__device__ float g_attn[NM*NHD];        /* [M, H*D] head outputs */

/* ---------------- f32x2 packed-FMA helpers (sm_103a) ---------------- */
__device__ __forceinline__ ull pack2(float x, float y) {
    ull r; asm("mov.b64 %0, {%1,%2};" : "=l"(r) : "f"(x), "f"(y)); return r;
}
__device__ __forceinline__ float2 unpack2(ull v) {
    float2 f; asm("mov.b64 {%0,%1}, %2;" : "=f"(f.x), "=f"(f.y) : "l"(v)); return f;
}
__device__ __forceinline__ void ffma2(ull &c, ull a, ull b) {
    asm("fma.rn.f32x2 %0, %1, %2, %0;" : "+l"(c) : "l"(a), "l"(b));
}

enum { MODE_Q = 0, MODE_K = 1, MODE_V = 2, MODE_L = 3, MODE_O = 4 };

/* =====================================================================
 *  SGEMM: C[M,N] = A[M,1024] @ W[1024,N] + bias, with epilogue/layout mode
 *  128x128 block tile, BK=8, 256 threads, 8x8 per-thread microtile (f32x2)
 * ===================================================================== */
__global__ void __launch_bounds__(256)
gemm_kernel(const float* __restrict__ A_in, const float* __restrict__ Wm,
            const float* __restrict__ bias, float* __restrict__ outp,
            int N, int mode)
{
    const int K = 1024;
    __shared__ float As[8][128];
    __shared__ float Bs[8][132];

    const float* __restrict__ A = (mode == MODE_O) ? g_attn : A_in;

    int tid = threadIdx.x;
    int m0 = blockIdx.y * 128;
    int n0 = blockIdx.x * 128;

    int ty = tid >> 4, tx = tid & 15;
    int mrow = ty * 8, ncol = tx * 8;

    int ar = tid >> 1;           /* 0..127 */
    int ak = (tid & 1) * 4;      /* 0 or 4 */
    int br = tid >> 5;           /* 0..7   */
    int bc = (tid & 31) * 4;     /* 0..124 */

    ull c2[8][4];
#pragma unroll
    for (int i = 0; i < 8; i++)
#pragma unroll
        for (int j = 0; j < 4; j++) c2[i][j] = 0ull;

    for (int k0 = 0; k0 < K; k0 += 8) {
        float4 av = *(const float4*)&A[(m0 + ar) * K + k0 + ak];
        float4 bv;
        if (n0 + bc + 3 < N) {
            bv = *(const float4*)&Wm[(k0 + br) * N + n0 + bc];
        } else {
            bv.x = (n0 + bc + 0 < N) ? Wm[(k0 + br) * N + n0 + bc + 0] : 0.f;
            bv.y = (n0 + bc + 1 < N) ? Wm[(k0 + br) * N + n0 + bc + 1] : 0.f;
            bv.z = (n0 + bc + 2 < N) ? Wm[(k0 + br) * N + n0 + bc + 2] : 0.f;
            bv.w = (n0 + bc + 3 < N) ? Wm[(k0 + br) * N + n0 + bc + 3] : 0.f;
        }
        __syncthreads();
        As[ak + 0][ar] = av.x;
        As[ak + 1][ar] = av.y;
        As[ak + 2][ar] = av.z;
        As[ak + 3][ar] = av.w;
        *(float4*)&Bs[br][bc] = bv;
        __syncthreads();

#pragma unroll
        for (int kk = 0; kk < 8; kk++) {
            float4 a0 = *(const float4*)&As[kk][mrow];
            float4 a1 = *(const float4*)&As[kk][mrow + 4];
            const float* bp = &Bs[kk][ncol];
            ull b0 = *(const ull*)(bp + 0);
            ull b1 = *(const ull*)(bp + 2);
            ull b2 = *(const ull*)(bp + 4);
            ull b3 = *(const ull*)(bp + 6);
            float a_[8] = {a0.x, a0.y, a0.z, a0.w, a1.x, a1.y, a1.z, a1.w};
#pragma unroll
            for (int i = 0; i < 8; i++) {
                ull ad = pack2(a_[i], a_[i]);
                ffma2(c2[i][0], ad, b0);
                ffma2(c2[i][1], ad, b1);
                ffma2(c2[i][2], ad, b2);
                ffma2(c2[i][3], ad, b3);
            }
        }
    }

    /* epilogue */
#pragma unroll
    for (int i = 0; i < 8; i++) {
        int m = m0 + mrow + i;
#pragma unroll
        for (int j = 0; j < 4; j++) {
            float2 v = unpack2(c2[i][j]);
#pragma unroll
            for (int hlf = 0; hlf < 2; hlf++) {
                int n = n0 + ncol + 2 * j + hlf;
                if (n >= N) continue;
                float c = ((hlf == 0) ? v.x : v.y) + bias[n];
                if (mode == MODE_Q || mode == MODE_K) {
                    float p = (c > 0.f) ? (c + 1.f) : expf(c);
                    int b = m >> 10, t = m & (NT - 1);
                    int h = n >> 6, d = n & 63;
                    float* dst = (mode == MODE_Q) ? g_Qp : g_Kp;
                    dst[((b * NH + h) * NT + t) * HD + d] = p;
                } else if (mode == MODE_V) {
                    int b = m >> 10, t = m & (NT - 1);
                    int h = n >> 6, d = n & 63;
                    g_V[((b * NH + h) * NT + t) * HD + d] = c;
                } else if (mode == MODE_L) {
                    g_logits[m * NHL + n] = c;
                } else { /* MODE_O */
                    outp[m * NHD + n] = c;
                }
            }
        }
    }
}

/* =====================================================================
 *  Softmax over L=12 per (b,h,t)
 * ===================================================================== */
__global__ void softmax_kernel()
{
    int id = blockIdx.x * blockDim.x + threadIdx.x;   /* 0 .. M*H-1 */
    if (id >= NM * NH) return;
    int m = id / NH, h = id % NH;
    const float* lg = &g_logits[m * NHL + h * NL];
    float mx = lg[0];
#pragma unroll
    for (int l = 1; l < NL; l++) mx = fmaxf(mx, lg[l]);
    float e[NL], s = 0.f;
#pragma unroll
    for (int l = 0; l < NL; l++) { e[l] = expf(lg[l] - mx); s += e[l]; }
    float inv = 1.f / s;
    int b = m >> 10, t = m & (NT - 1);
    float* wp = &g_w[((b * NH + h) * NT + t) * NL];
#pragma unroll
    for (int l = 0; l < NL; l++) wp[l] = e[l] * inv;
}

/* =====================================================================
 *  Attention: per (b,h), query tile 128 x key tile 64, fp32 (f32x2)
 *  S = Qp Kp^T ; S' = S * w[i, lev(i,j)] * (j<=i) ; O = S' V ; den = rowsum
 *  lev(i,j) = 31 - clz(j ^ (i+1))    (replaces the level_masks einsum)
 * ===================================================================== */
#define QT 128
#define KT 64
#define SQ 132   /* Qt row stride  */
#define SK 68    /* Kt row stride  */
#define SV 68    /* Vs row stride  */
#define SS 130   /* Sst row stride */
#define ATTN_SMEM_FLOATS (64*SQ + 64*SK + 64*SV + 64*SS + QT*NL + QT)
#define ATTN_SMEM_BYTES  (ATTN_SMEM_FLOATS * 4)

__global__ void __launch_bounds__(256)
attn_kernel()
{
    extern __shared__ float sm[];
    float* Qt  = sm;                 /* [64][SQ]  transposed: Qt[d][q]  */
    float* Kt  = Qt  + 64 * SQ;      /* [64][SK]  transposed: Kt[d][j]  */
    float* Vs  = Kt  + 64 * SK;      /* [64][SV]  Vs[j][e]              */
    float* Sst = Vs  + 64 * SV;      /* [64][SS]  Sst[j][q] (weighted)  */
    float* Ws  = Sst + 64 * SS;      /* [128][12] per-query level wts   */
    float* sden = Ws + QT * NL;      /* [128]                            */

    int tid = threadIdx.x;
    int bh = blockIdx.y;
    int qt = blockIdx.x;
    int i0 = qt * QT;

    const float* __restrict__ Qg = g_Qp + (size_t)bh * NT * HD;
    const float* __restrict__ Kg = g_Kp + (size_t)bh * NT * HD;
    const float* __restrict__ Vg = g_V  + (size_t)bh * NT * HD;
    const float* __restrict__ wg = g_w  + (size_t)bh * NT * NL;

    /* load Q tile (transposed) */
#pragma unroll
    for (int r = 0; r < 8; r++) {
        int f = r * 256 + tid;          /* 0..2047 */
        int q = f >> 4;
        int d4 = (f & 15) * 4;
        float4 v = *(const float4*)&Qg[(i0 + q) * HD + d4];
        Qt[(d4 + 0) * SQ + q] = v.x;
        Qt[(d4 + 1) * SQ + q] = v.y;
        Qt[(d4 + 2) * SQ + q] = v.z;
        Qt[(d4 + 3) * SQ + q] = v.w;
    }
    /* load per-query level weights (contiguous) */
#pragma unroll
    for (int r = 0; r < 6; r++) {
        int f = r * 256 + tid;          /* 0..1535 */
        Ws[f] = wg[i0 * NL + f];
    }
    if (tid < QT) sden[tid] = 0.f;

    int qg = tid >> 4;                  /* 0..15 -> 8 queries  */
    int sg = tid & 15;                  /* 0..15 -> 4 cols     */
    int q0 = qg * 8;

    ull o2[4][4];                       /* [qpair][e] output accum */
#pragma unroll
    for (int p = 0; p < 4; p++)
#pragma unroll
        for (int e = 0; e < 4; e++) o2[p][e] = 0ull;

    int ntiles = 2 * qt + 2;
    for (int jt = 0; jt < ntiles; jt++) {
        int j0g = jt * KT;
        __syncthreads();
        /* load K (transposed) and V (direct) tiles */
#pragma unroll
        for (int r = 0; r < 4; r++) {
            int f = r * 256 + tid;      /* 0..1023 */
            int j = f >> 4;
            int d4 = (f & 15) * 4;
            float4 kv = *(const float4*)&Kg[(j0g + j) * HD + d4];
            Kt[(d4 + 0) * SK + j] = kv.x;
            Kt[(d4 + 1) * SK + j] = kv.y;
            Kt[(d4 + 2) * SK + j] = kv.z;
            Kt[(d4 + 3) * SK + j] = kv.w;
            *(float4*)&Vs[j * SV + d4] = *(const float4*)&Vg[(j0g + j) * HD + d4];
        }
        __syncthreads();

        /* ---- phase A: S tile (8q x 4j per thread), packed along q-pairs ---- */
        int j0 = sg * 4;
        ull acc[4][4];
#pragma unroll
        for (int p = 0; p < 4; p++)
#pragma unroll
            for (int j = 0; j < 4; j++) acc[p][j] = 0ull;

#pragma unroll 8
        for (int d = 0; d < 64; d++) {
            const float* qp_ = &Qt[d * SQ + q0];
            ull a0 = *(const ull*)(qp_ + 0);
            ull a1 = *(const ull*)(qp_ + 2);
            ull a2 = *(const ull*)(qp_ + 4);
            ull a3 = *(const ull*)(qp_ + 6);
            float4 b4 = *(const float4*)&Kt[d * SK + j0];
            ull bd0 = pack2(b4.x, b4.x);
            ull bd1 = pack2(b4.y, b4.y);
            ull bd2 = pack2(b4.z, b4.z);
            ull bd3 = pack2(b4.w, b4.w);
            ffma2(acc[0][0], a0, bd0); ffma2(acc[0][1], a0, bd1);
            ffma2(acc[0][2], a0, bd2); ffma2(acc[0][3], a0, bd3);
            ffma2(acc[1][0], a1, bd0); ffma2(acc[1][1], a1, bd1);
            ffma2(acc[1][2], a1, bd2); ffma2(acc[1][3], a1, bd3);
            ffma2(acc[2][0], a2, bd0); ffma2(acc[2][1], a2, bd1);
            ffma2(acc[2][2], a2, bd2); ffma2(acc[2][3], a2, bd3);
            ffma2(acc[3][0], a3, bd0); ffma2(acc[3][1], a3, bd1);
            ffma2(acc[3][2], a3, bd2); ffma2(acc[3][3], a3, bd3);
        }

        /* weight by w[i, lev(i,j)], mask j<=i, store transposed */
#pragma unroll
        for (int p = 0; p < 4; p++) {
            int ql0 = q0 + 2 * p;
            int ie = i0 + ql0;
            int io = ie + 1;
#pragma unroll
            for (int j = 0; j < 4; j++) {
                int jg_ = j0g + j0 + j;
                float2 s = unpack2(acc[p][j]);
                float se = 0.f, so = 0.f;
                if (jg_ <= ie) {
                    int lev = 31 - __clz(jg_ ^ (ie + 1));
                    se = s.x * Ws[ql0 * NL + lev];
                }
                if (jg_ <= io) {
                    int lev = 31 - __clz(jg_ ^ (io + 1));
                    so = s.y * Ws[(ql0 + 1) * NL + lev];
                }
                *(ull*)&Sst[(j0 + j) * SS + ql0] = pack2(se, so);
            }
        }
        __syncthreads();

        /* denominator partial sums: one thread per query row */
        if (tid < QT) {
            float dsum = 0.f;
#pragma unroll 8
            for (int j = 0; j < KT; j++) dsum += Sst[j * SS + tid];
            sden[tid] += dsum;
        }

        /* ---- phase B: O += S' @ V (8q x 4e per thread) ---- */
        int e0 = sg * 4;
#pragma unroll 8
        for (int j = 0; j < KT; j++) {
            const float* sp = &Sst[j * SS + q0];
            ull a0 = *(const ull*)(sp + 0);
            ull a1 = *(const ull*)(sp + 2);
            ull a2 = *(const ull*)(sp + 4);
            ull a3 = *(const ull*)(sp + 6);
            float4 b4 = *(const float4*)&Vs[j * SV + e0];
            ull bd0 = pack2(b4.x, b4.x);
            ull bd1 = pack2(b4.y, b4.y);
            ull bd2 = pack2(b4.z, b4.z);
            ull bd3 = pack2(b4.w, b4.w);
            ffma2(o2[0][0], a0, bd0); ffma2(o2[0][1], a0, bd1);
            ffma2(o2[0][2], a0, bd2); ffma2(o2[0][3], a0, bd3);
            ffma2(o2[1][0], a1, bd0); ffma2(o2[1][1], a1, bd1);
            ffma2(o2[1][2], a1, bd2); ffma2(o2[1][3], a1, bd3);
            ffma2(o2[2][0], a2, bd0); ffma2(o2[2][1], a2, bd1);
            ffma2(o2[2][2], a2, bd2); ffma2(o2[2][3], a2, bd3);
            ffma2(o2[3][0], a3, bd0); ffma2(o2[3][1], a3, bd1);
            ffma2(o2[3][2], a3, bd2); ffma2(o2[3][3], a3, bd3);
        }
    }

    __syncthreads();   /* sden complete */

    int b = bh / NH, h = bh % NH;
    int e0 = sg * 4;
#pragma unroll
    for (int p = 0; p < 4; p++) {
        int qle = q0 + 2 * p;
        float re = 1.f / fmaxf(sden[qle], 1e-6f);
        float ro = 1.f / fmaxf(sden[qle + 1], 1e-6f);
        int me = (b * NT + i0 + qle);
#pragma unroll
        for (int e = 0; e < 4; e++) {
            float2 v = unpack2(o2[p][e]);
            g_attn[me * NHD + h * HD + e0 + e]       = v.x * re;
            g_attn[(me + 1) * NHD + h * HD + e0 + e] = v.y * ro;
        }
    }
}

/* ===================================================================== */
extern "C" void kernel_launch(void* const* d_in, const int* in_sizes, int n_in,
                              void* d_out, int out_size)
{
    const float* x  = (const float*)d_in[0];
    const float* qw = (const float*)d_in[1];
    const float* qb = (const float*)d_in[2];
    const float* kw = (const float*)d_in[3];
    const float* kb = (const float*)d_in[4];
    const float* vw = (const float*)d_in[5];
    const float* vb = (const float*)d_in[6];
    const float* lw = (const float*)d_in[7];
    const float* lb = (const float*)d_in[8];
    const float* ow = (const float*)d_in[9];
    const float* ob = (const float*)d_in[10];
    /* d_in[11] = level_masks — replaced analytically by lev(i,j) */
    float* out = (float*)d_out;

    cudaFuncSetAttribute(attn_kernel, cudaFuncAttributeMaxDynamicSharedMemorySize,
                         ATTN_SMEM_BYTES);

    dim3 thr(256);
    gemm_kernel<<<dim3(8, 16), thr>>>(x, qw, qb, nullptr, NHD, MODE_Q);
    gemm_kernel<<<dim3(8, 16), thr>>>(x, kw, kb, nullptr, NHD, MODE_K);
    gemm_kernel<<<dim3(8, 16), thr>>>(x, vw, vb, nullptr, NHD, MODE_V);
    gemm_kernel<<<dim3(2, 16), thr>>>(x, lw, lb, nullptr, NHL, MODE_L);
    softmax_kernel<<<(NM * NH + 255) / 256, 256>>>();
    attn_kernel<<<dim3(NT / QT, NB * NH), 256, ATTN_SMEM_BYTES>>>();
    gemm_kernel<<<dim3(8, 16), thr>>>(nullptr, ow, ob, out, NHD, MODE_O);
}

// round 4
// speedup vs baseline: 1.8039x; 1.8039x over previous
#include <cuda_runtime.h>
#include <math.h>

#define NB 2
#define NT 1024
#define NH 16
#define HD 64
#define NL 12
#define NM (NB*NT)        /* 2048 */
#define NHL (NH*NL)       /* 192  */
#define NHD (NH*HD)       /* 1024 */

/* ---------------- scratch ---------------- */
__device__ float g_Qp[NB*NH*NT*HD];     /* tf32-rounded phi(Q), [B,H,T,D] */
__device__ float g_Kp[NB*NH*NT*HD];     /* tf32-rounded phi(K)            */
__device__ float g_V [NB*NH*NT*HD];     /* tf32-rounded V                 */
__device__ float g_logits[NM*NHL];
__device__ float g_w[NB*NH*NT*NL];
__device__ float g_attn[NM*NHD];

/* ---------------- helpers ---------------- */
__device__ __forceinline__ unsigned f2tf(float f){
    unsigned u; asm("cvt.rna.tf32.f32 %0, %1;" : "=r"(u) : "f"(f)); return u;
}
__device__ __forceinline__ void mma8(float* c, const unsigned* a, const unsigned* b){
    asm volatile("mma.sync.aligned.m16n8k8.row.col.f32.tf32.tf32.f32 "
        "{%0,%1,%2,%3}, {%4,%5,%6,%7}, {%8,%9}, {%0,%1,%2,%3};"
        : "+f"(c[0]),"+f"(c[1]),"+f"(c[2]),"+f"(c[3])
        : "r"(a[0]),"r"(a[1]),"r"(a[2]),"r"(a[3]),"r"(b[0]),"r"(b[1]));
}
/* permute k within 8-block so frag cols (t, t+4) sit adjacent -> LDS.64 */
__device__ __forceinline__ int pk8(int c){ return (c & ~7) | ((c&3)<<1) | ((c>>2)&1); }

enum { MODE_Q = 0, MODE_K = 1, MODE_V = 2, MODE_L = 3, MODE_O = 4 };

/* =====================================================================
 *  tf32 tensor-core GEMM: C[M=2048, N] = A[M,1024] @ W[1024,N] + bias
 *  128x128x32 tile, double-buffered, 8 warps (warp tile 64x32, m16n8k8)
 * ===================================================================== */
#define GASTR 36
#define GSTG (128*GASTR)                 /* floats per operand per stage */
#define GEMM_SMEM (4*GSTG*4)             /* 2 ops x 2 stages, bytes      */

__global__ void __launch_bounds__(256,1)
gemm_tc(const float* __restrict__ A_in,
        const float* __restrict__ W0, const float* __restrict__ W1, const float* __restrict__ W2,
        const float* __restrict__ Bi0, const float* __restrict__ Bi1, const float* __restrict__ Bi2,
        float* __restrict__ outp, int N, int mode0)
{
    extern __shared__ float sm[];
    float* As = sm;            /* [2][128][GASTR] rows m, perm-k cols  */
    float* Bs = sm + 2*GSTG;   /* [2][128][GASTR] rows n, perm-k cols  */

    const int z = blockIdx.z;
    const int mode = mode0 + z;
    const float* __restrict__ W    = (z==0)?W0 :(z==1)?W1 :W2;
    const float* __restrict__ bias = (z==0)?Bi0:(z==1)?Bi1:Bi2;
    const float* __restrict__ A = (mode==MODE_O) ? g_attn : A_in;

    const int tid = threadIdx.x;
    const int m0 = blockIdx.y*128, n0 = blockIdx.x*128;
    const int wid = tid>>5, lane = tid&31, g = lane>>2, tg = lane&3;
    const int wm = wid>>2, wn = wid&3;

    float acc[4][4][4];
#pragma unroll
    for (int mt=0; mt<4; mt++)
#pragma unroll
        for (int nt=0; nt<4; nt++)
#pragma unroll
            for (int r=0; r<4; r++) acc[mt][nt][r] = 0.f;

    /* global-load index precompute */
    int arow[4], akq[4], bk[4], bnq[4];
#pragma unroll
    for (int r=0; r<4; r++) {
        int fid = r*256 + tid;
        arow[r] = fid>>3;  akq[r] = (fid&7)<<2;    /* A: 128 rows x 8 float4 */
        bk[r]   = fid>>5;  bnq[r] = (fid&31)<<2;   /* B: 32 k-rows x 32 float4 */
    }

    float4 pa[4], pb[4];
    /* prologue: stage 0 */
#pragma unroll
    for (int r=0; r<4; r++) {
        pa[r] = *(const float4*)&A[(size_t)(m0+arow[r])*1024 + akq[r]];
        if (n0 + bnq[r] < N)
            pb[r] = *(const float4*)&W[(size_t)bk[r]*N + n0 + bnq[r]];
        else { pb[r].x=pb[r].y=pb[r].z=pb[r].w=0.f; }
    }
#pragma unroll
    for (int r=0; r<4; r++) {
        float* ap = &As[arow[r]*GASTR];
        ap[pk8(akq[r]+0)] = __uint_as_float(f2tf(pa[r].x));
        ap[pk8(akq[r]+1)] = __uint_as_float(f2tf(pa[r].y));
        ap[pk8(akq[r]+2)] = __uint_as_float(f2tf(pa[r].z));
        ap[pk8(akq[r]+3)] = __uint_as_float(f2tf(pa[r].w));
        int pc = pk8(bk[r]);
        Bs[(bnq[r]+0)*GASTR + pc] = __uint_as_float(f2tf(pb[r].x));
        Bs[(bnq[r]+1)*GASTR + pc] = __uint_as_float(f2tf(pb[r].y));
        Bs[(bnq[r]+2)*GASTR + pc] = __uint_as_float(f2tf(pb[r].z));
        Bs[(bnq[r]+3)*GASTR + pc] = __uint_as_float(f2tf(pb[r].w));
    }
    __syncthreads();

    for (int ks = 0; ks < 32; ks++) {
        if (ks < 31) {
            int k0 = (ks+1)*32;
#pragma unroll
            for (int r=0; r<4; r++) {
                pa[r] = *(const float4*)&A[(size_t)(m0+arow[r])*1024 + k0 + akq[r]];
                if (n0 + bnq[r] < N)
                    pb[r] = *(const float4*)&W[(size_t)(k0+bk[r])*N + n0 + bnq[r]];
                else { pb[r].x=pb[r].y=pb[r].z=pb[r].w=0.f; }
            }
        }
        const float* As_ = As + (ks&1)*GSTG;
        const float* Bs_ = Bs + (ks&1)*GSTG;
#pragma unroll
        for (int k8 = 0; k8 < 4; k8++) {
            unsigned a[4][4];
#pragma unroll
            for (int mt=0; mt<4; mt++) {
                int rb = wm*64 + mt*16;
                uint2 p0 = *(const uint2*)&As_[(rb+g  )*GASTR + k8*8 + 2*tg];
                uint2 p1 = *(const uint2*)&As_[(rb+g+8)*GASTR + k8*8 + 2*tg];
                a[mt][0]=p0.x; a[mt][2]=p0.y; a[mt][1]=p1.x; a[mt][3]=p1.y;
            }
#pragma unroll
            for (int nt=0; nt<4; nt++) {
                uint2 bb = *(const uint2*)&Bs_[(wn*32+nt*8+g)*GASTR + k8*8 + 2*tg];
                unsigned b[2] = {bb.x, bb.y};
#pragma unroll
                for (int mt=0; mt<4; mt++) mma8(acc[mt][nt], a[mt], b);
            }
        }
        if (ks < 31) {
            int st = ((ks+1)&1)*GSTG;
#pragma unroll
            for (int r=0; r<4; r++) {
                float* ap = &As[st + arow[r]*GASTR];
                ap[pk8(akq[r]+0)] = __uint_as_float(f2tf(pa[r].x));
                ap[pk8(akq[r]+1)] = __uint_as_float(f2tf(pa[r].y));
                ap[pk8(akq[r]+2)] = __uint_as_float(f2tf(pa[r].z));
                ap[pk8(akq[r]+3)] = __uint_as_float(f2tf(pa[r].w));
                int pc = pk8(bk[r]);
                Bs[st + (bnq[r]+0)*GASTR + pc] = __uint_as_float(f2tf(pb[r].x));
                Bs[st + (bnq[r]+1)*GASTR + pc] = __uint_as_float(f2tf(pb[r].y));
                Bs[st + (bnq[r]+2)*GASTR + pc] = __uint_as_float(f2tf(pb[r].z));
                Bs[st + (bnq[r]+3)*GASTR + pc] = __uint_as_float(f2tf(pb[r].w));
            }
        }
        __syncthreads();
    }

    /* epilogue */
#pragma unroll
    for (int mt=0; mt<4; mt++) {
#pragma unroll
        for (int nt=0; nt<4; nt++) {
#pragma unroll
            for (int r=0; r<4; r++) {
                int m = m0 + wm*64 + mt*16 + g + ((r>>1)<<3);
                int n = n0 + wn*32 + nt*8 + 2*tg + (r&1);
                if (n >= N) continue;
                float c = acc[mt][nt][r] + bias[n];
                if (mode == MODE_Q || mode == MODE_K) {
                    float p = (c > 0.f) ? (c + 1.f) : expf(c);
                    int b = m >> 10, t = m & (NT-1);
                    int h = n >> 6,  d = n & 63;
                    float* dst = (mode == MODE_Q) ? g_Qp : g_Kp;
                    dst[((b*NH + h)*NT + t)*HD + d] = __uint_as_float(f2tf(p));
                } else if (mode == MODE_V) {
                    int b = m >> 10, t = m & (NT-1);
                    int h = n >> 6,  d = n & 63;
                    g_V[((b*NH + h)*NT + t)*HD + d] = __uint_as_float(f2tf(c));
                } else if (mode == MODE_L) {
                    g_logits[m*NHL + n] = c;
                } else { /* MODE_O */
                    outp[m*NHD + n] = c;
                }
            }
        }
    }
}

/* =====================================================================
 *  Softmax over L=12 per (b,h,t)
 * ===================================================================== */
__global__ void softmax_kernel()
{
    int id = blockIdx.x*blockDim.x + threadIdx.x;
    if (id >= NM*NH) return;
    int m = id / NH, h = id % NH;
    const float* lg = &g_logits[m*NHL + h*NL];
    float mx = lg[0];
#pragma unroll
    for (int l=1; l<NL; l++) mx = fmaxf(mx, lg[l]);
    float e[NL], s = 0.f;
#pragma unroll
    for (int l=0; l<NL; l++) { e[l] = expf(lg[l]-mx); s += e[l]; }
    float inv = 1.f/s;
    int b = m >> 10, t = m & (NT-1);
    float* wp = &g_w[((b*NH + h)*NT + t)*NL];
#pragma unroll
    for (int l=0; l<NL; l++) wp[l] = e[l]*inv;
}

/* =====================================================================
 *  Attention (tf32 mma): per (bh, qtile 128), key tiles of 128
 *  S = Qp Kp^T (mma) -> weight in regs -> Ssm (tf32) -> O += Ssm @ V (mma)
 * ===================================================================== */
#define AQSTR 68
#define AJSTR 132
#define A_QS (128*AQSTR)
#define A_KS (128*AQSTR)
#define A_VS (64*AJSTR)
#define A_SS (128*AJSTR)
#define A_WS (128*NL)
#define ATTN_SMEM ((A_QS + A_KS + A_VS + A_SS + A_WS + 128)*4)

__global__ void __launch_bounds__(256,1)
attn_tc()
{
    extern __shared__ float sm[];
    float* Qs  = sm;               /* [128][AQSTR] rows i, perm-d cols */
    float* Ks  = Qs  + A_QS;       /* [128][AQSTR] rows j, perm-d cols */
    float* Vst = Ks  + A_KS;       /* [64][AJSTR]  rows e, perm-j cols */
    float* Ssm = Vst + A_VS;       /* [128][AJSTR] rows i, perm-j cols */
    float* Ws  = Ssm + A_SS;       /* [128][12]                         */
    float* den = Ws  + A_WS;       /* [128]                             */

    const int tid = threadIdx.x;
    const int wid = tid>>5, lane = tid&31, g = lane>>2, tg = lane&3;
    const int wm = wid>>1, wn = wid&1;      /* S: 4x2 warps (32 x 64)    */
    const int bh = blockIdx.y;
    const int qt = blockIdx.x;
    const int i0 = qt*128;

    const float* __restrict__ Qg = g_Qp + (size_t)bh*NT*HD;
    const float* __restrict__ Kg = g_Kp + (size_t)bh*NT*HD;
    const float* __restrict__ Vg = g_V  + (size_t)bh*NT*HD;
    const float* __restrict__ wg = g_w  + (size_t)bh*NT*NL;

    /* Q tile + level weights + den init */
#pragma unroll
    for (int r=0; r<8; r++) {
        int fid = r*256 + tid;              /* 0..2047 */
        int q = fid>>4, dq = (fid&15)<<2;
        float4 v = *(const float4*)&Qg[(size_t)(i0+q)*HD + dq];
        float* qp = &Qs[q*AQSTR];
        qp[pk8(dq+0)] = v.x; qp[pk8(dq+1)] = v.y;
        qp[pk8(dq+2)] = v.z; qp[pk8(dq+3)] = v.w;
    }
#pragma unroll
    for (int r=0; r<6; r++) { int fid = r*256+tid; Ws[fid] = wg[i0*NL + fid]; }
    if (tid < 128) den[tid] = 0.f;

    float oacc[2][4][4];                    /* O warp tile 32 x 32 */
#pragma unroll
    for (int mt=0; mt<2; mt++)
#pragma unroll
        for (int nt=0; nt<4; nt++)
#pragma unroll
            for (int r=0; r<4; r++) oacc[mt][nt][r] = 0.f;

    const int ntiles = qt + 1;
    for (int jt = 0; jt < ntiles; jt++) {
        const int j0g = jt*128;
        __syncthreads();                    /* prior reads of Ks/Vst/Ssm done */
#pragma unroll
        for (int r=0; r<8; r++) {
            int fid = r*256 + tid;
            int j = fid>>4, dq = (fid&15)<<2;
            float4 kv = *(const float4*)&Kg[(size_t)(j0g+j)*HD + dq];
            float* kp = &Ks[j*AQSTR];
            kp[pk8(dq+0)] = kv.x; kp[pk8(dq+1)] = kv.y;
            kp[pk8(dq+2)] = kv.z; kp[pk8(dq+3)] = kv.w;
            /* V transposed: Vst[e][perm(j)] */
            float4 vv = *(const float4*)&Vg[(size_t)(j0g+j)*HD + dq];
            int pj = pk8(j);
            Vst[(dq+0)*AJSTR + pj] = vv.x;
            Vst[(dq+1)*AJSTR + pj] = vv.y;
            Vst[(dq+2)*AJSTR + pj] = vv.z;
            Vst[(dq+3)*AJSTR + pj] = vv.w;
        }
        __syncthreads();

        /* ---- S = Q K^T : warp tile 32 x 64 ---- */
        float sacc[2][8][4];
#pragma unroll
        for (int mt=0; mt<2; mt++)
#pragma unroll
            for (int nt=0; nt<8; nt++)
#pragma unroll
                for (int r=0; r<4; r++) sacc[mt][nt][r] = 0.f;

#pragma unroll
        for (int k8=0; k8<8; k8++) {
            unsigned a[2][4];
#pragma unroll
            for (int mt=0; mt<2; mt++) {
                int rb = wm*32 + mt*16;
                uint2 p0 = *(const uint2*)&Qs[(rb+g  )*AQSTR + k8*8 + 2*tg];
                uint2 p1 = *(const uint2*)&Qs[(rb+g+8)*AQSTR + k8*8 + 2*tg];
                a[mt][0]=p0.x; a[mt][2]=p0.y; a[mt][1]=p1.x; a[mt][3]=p1.y;
            }
#pragma unroll
            for (int nt=0; nt<8; nt++) {
                uint2 bb = *(const uint2*)&Ks[(wn*64+nt*8+g)*AQSTR + k8*8 + 2*tg];
                unsigned b[2] = {bb.x, bb.y};
                mma8(sacc[0][nt], a[0], b);
                mma8(sacc[1][nt], a[1], b);
            }
        }

        /* ---- weight + mask + store Ssm + row sums ---- */
        float rs[2][2] = {{0.f,0.f},{0.f,0.f}};
#pragma unroll
        for (int mt=0; mt<2; mt++) {
#pragma unroll
            for (int nt=0; nt<8; nt++) {
#pragma unroll
                for (int r=0; r<4; r++) {
                    int il = wm*32 + mt*16 + g + ((r>>1)<<3);
                    int jl = wn*64 + nt*8 + 2*tg + (r&1);
                    int i = i0 + il, j = j0g + jl;
                    float v = 0.f;
                    if (j <= i) {
                        int lev = 31 - __clz(j ^ (i+1));
                        v = sacc[mt][nt][r] * Ws[il*NL + lev];
                    }
                    rs[mt][r>>1] += v;
                    Ssm[il*AJSTR + pk8(jl)] = __uint_as_float(f2tf(v));
                }
            }
        }
#pragma unroll
        for (int mt=0; mt<2; mt++) {
#pragma unroll
            for (int hf=0; hf<2; hf++) {
                float v = rs[mt][hf];
                v += __shfl_xor_sync(0xFFFFFFFFu, v, 1);
                v += __shfl_xor_sync(0xFFFFFFFFu, v, 2);
                if (tg == 0)
                    atomicAdd(&den[wm*32 + mt*16 + g + hf*8], v);
            }
        }
        __syncthreads();

        /* ---- O += Ssm @ V : warp tile 32 x 32, k over 128 j's ---- */
#pragma unroll
        for (int k8=0; k8<16; k8++) {
            unsigned a[2][4];
#pragma unroll
            for (int mt=0; mt<2; mt++) {
                int rb = wm*32 + mt*16;
                uint2 p0 = *(const uint2*)&Ssm[(rb+g  )*AJSTR + k8*8 + 2*tg];
                uint2 p1 = *(const uint2*)&Ssm[(rb+g+8)*AJSTR + k8*8 + 2*tg];
                a[mt][0]=p0.x; a[mt][2]=p0.y; a[mt][1]=p1.x; a[mt][3]=p1.y;
            }
#pragma unroll
            for (int nt=0; nt<4; nt++) {
                uint2 bb = *(const uint2*)&Vst[(wn*32+nt*8+g)*AJSTR + k8*8 + 2*tg];
                unsigned b[2] = {bb.x, bb.y};
                mma8(oacc[0][nt], a[0], b);
                mma8(oacc[1][nt], a[1], b);
            }
        }
    }

    __syncthreads();   /* den atomics complete */

    const int b = bh >> 4, h = bh & 15;
    float rcp[2][2];
#pragma unroll
    for (int mt=0; mt<2; mt++)
#pragma unroll
        for (int hf=0; hf<2; hf++)
            rcp[mt][hf] = 1.f / fmaxf(den[wm*32 + mt*16 + g + hf*8], 1e-6f);
#pragma unroll
    for (int mt=0; mt<2; mt++) {
#pragma unroll
        for (int nt=0; nt<4; nt++) {
#pragma unroll
            for (int r=0; r<4; r++) {
                int il = wm*32 + mt*16 + g + ((r>>1)<<3);
                int e  = wn*32 + nt*8 + 2*tg + (r&1);
                g_attn[(size_t)(b*NT + i0 + il)*NHD + h*HD + e] =
                    oacc[mt][nt][r] * rcp[mt][r>>1];
            }
        }
    }
}

/* ===================================================================== */
extern "C" void kernel_launch(void* const* d_in, const int* in_sizes, int n_in,
                              void* d_out, int out_size)
{
    const float* x  = (const float*)d_in[0];
    const float* qw = (const float*)d_in[1];
    const float* qb = (const float*)d_in[2];
    const float* kw = (const float*)d_in[3];
    const float* kb = (const float*)d_in[4];
    const float* vw = (const float*)d_in[5];
    const float* vb = (const float*)d_in[6];
    const float* lw = (const float*)d_in[7];
    const float* lb = (const float*)d_in[8];
    const float* ow = (const float*)d_in[9];
    const float* ob = (const float*)d_in[10];
    float* out = (float*)d_out;

    cudaFuncSetAttribute(gemm_tc, cudaFuncAttributeMaxDynamicSharedMemorySize, GEMM_SMEM);
    cudaFuncSetAttribute(attn_tc, cudaFuncAttributeMaxDynamicSharedMemorySize, ATTN_SMEM);

    /* fused Q/K/V projections (z selects weight) */
    gemm_tc<<<dim3(8,16,3), 256, GEMM_SMEM>>>(x, qw, kw, vw, qb, kb, vb,
                                              nullptr, NHD, MODE_Q);
    /* level logits (N=192) */
    gemm_tc<<<dim3(2,16,1), 256, GEMM_SMEM>>>(x, lw, lw, lw, lb, lb, lb,
                                              nullptr, NHL, MODE_L);
    softmax_kernel<<<(NM*NH + 255)/256, 256>>>();
    attn_tc<<<dim3(8, NB*NH), 256, ATTN_SMEM>>>();
    /* output projection */
    gemm_tc<<<dim3(8,16,1), 256, GEMM_SMEM>>>(nullptr, ow, ow, ow, ob, ob, ob,
                                              out, NHD, MODE_O);
}

// round 5
// speedup vs baseline: 1.9039x; 1.0554x over previous
#include <cuda_runtime.h>
#include <math.h>

#define NB 2
#define NT 1024
#define NH 16
#define HD 64
#define NL 12
#define NM (NB*NT)        /* 2048 */
#define NHL (NH*NL)       /* 192  */
#define NHD (NH*HD)       /* 1024 */

/* ---------------- scratch ---------------- */
__device__ float g_Qp[NB*NH*NT*HD];
__device__ float g_Kp[NB*NH*NT*HD];
__device__ float g_V [NB*NH*NT*HD];
__device__ float g_logits[NM*NHL];
__device__ float g_w[NB*NH*NT*NL];
__device__ float g_attn[NM*NHD];

/* ---------------- helpers ---------------- */
__device__ __forceinline__ unsigned f2tf(float f){
    unsigned u; asm("cvt.rna.tf32.f32 %0, %1;" : "=r"(u) : "f"(f)); return u;
}
__device__ __forceinline__ void mma8(float* c, const unsigned* a, const unsigned* b){
    asm volatile("mma.sync.aligned.m16n8k8.row.col.f32.tf32.tf32.f32 "
        "{%0,%1,%2,%3}, {%4,%5,%6,%7}, {%8,%9}, {%0,%1,%2,%3};"
        : "+f"(c[0]),"+f"(c[1]),"+f"(c[2]),"+f"(c[3])
        : "r"(a[0]),"r"(a[1]),"r"(a[2]),"r"(a[3]),"r"(b[0]),"r"(b[1]));
}
__device__ __forceinline__ int pk8(int c){ return (c & ~7) | ((c&3)<<1) | ((c>>2)&1); }

enum { MODE_Q = 0, MODE_K = 1, MODE_V = 2, MODE_L = 3, MODE_O = 4 };

/* =====================================================================
 *  tf32 tensor-core GEMM: C[M=2048, N] = A[M,1024] @ W[1024,N] + bias
 *  128x128x32 tile, double-buffered, 8 warps, 2 blocks/SM
 * ===================================================================== */
#define GASTR 36
#define GSTG (128*GASTR)
#define GEMM_SMEM (4*GSTG*4)

__global__ void __launch_bounds__(256,2)
gemm_tc(const float* __restrict__ A_in,
        const float* __restrict__ W0, const float* __restrict__ W1,
        const float* __restrict__ W2, const float* __restrict__ W3,
        const float* __restrict__ Bi0, const float* __restrict__ Bi1,
        const float* __restrict__ Bi2, const float* __restrict__ Bi3,
        float* __restrict__ outp, int Npar, int mode0)
{
    extern __shared__ float sm[];
    float* As = sm;
    float* Bs = sm + 2*GSTG;

    const int z = blockIdx.z;
    const int mode = mode0 + z;
    const int N = (mode == MODE_L) ? NHL : Npar;
    const int n0 = blockIdx.x*128;
    if (n0 >= N) return;                 /* early-exit for fused L tile */
    const float* __restrict__ W    = (z==0)?W0 :(z==1)?W1 :(z==2)?W2 :W3;
    const float* __restrict__ bias = (z==0)?Bi0:(z==1)?Bi1:(z==2)?Bi2:Bi3;
    const float* __restrict__ A = (mode==MODE_O) ? g_attn : A_in;

    const int tid = threadIdx.x;
    const int m0 = blockIdx.y*128;
    const int wid = tid>>5, lane = tid&31, g = lane>>2, tg = lane&3;
    const int wm = wid>>2, wn = wid&3;

    float acc[4][4][4];
#pragma unroll
    for (int mt=0; mt<4; mt++)
#pragma unroll
        for (int nt=0; nt<4; nt++)
#pragma unroll
            for (int r=0; r<4; r++) acc[mt][nt][r] = 0.f;

    int arow[4], akq[4], bk[4], bnq[4];
#pragma unroll
    for (int r=0; r<4; r++) {
        int fid = r*256 + tid;
        arow[r] = fid>>3;  akq[r] = (fid&7)<<2;
        bk[r]   = fid>>5;  bnq[r] = (fid&31)<<2;
    }

    float4 pa[4], pb[4];
#pragma unroll
    for (int r=0; r<4; r++) {
        pa[r] = *(const float4*)&A[(size_t)(m0+arow[r])*1024 + akq[r]];
        if (n0 + bnq[r] < N)
            pb[r] = *(const float4*)&W[(size_t)bk[r]*N + n0 + bnq[r]];
        else { pb[r].x=pb[r].y=pb[r].z=pb[r].w=0.f; }
    }
#pragma unroll
    for (int r=0; r<4; r++) {
        float* ap = &As[arow[r]*GASTR];
        ap[pk8(akq[r]+0)] = __uint_as_float(f2tf(pa[r].x));
        ap[pk8(akq[r]+1)] = __uint_as_float(f2tf(pa[r].y));
        ap[pk8(akq[r]+2)] = __uint_as_float(f2tf(pa[r].z));
        ap[pk8(akq[r]+3)] = __uint_as_float(f2tf(pa[r].w));
        int pc = pk8(bk[r]);
        Bs[(bnq[r]+0)*GASTR + pc] = __uint_as_float(f2tf(pb[r].x));
        Bs[(bnq[r]+1)*GASTR + pc] = __uint_as_float(f2tf(pb[r].y));
        Bs[(bnq[r]+2)*GASTR + pc] = __uint_as_float(f2tf(pb[r].z));
        Bs[(bnq[r]+3)*GASTR + pc] = __uint_as_float(f2tf(pb[r].w));
    }
    __syncthreads();

    for (int ks = 0; ks < 32; ks++) {
        if (ks < 31) {
            int k0 = (ks+1)*32;
#pragma unroll
            for (int r=0; r<4; r++) {
                pa[r] = *(const float4*)&A[(size_t)(m0+arow[r])*1024 + k0 + akq[r]];
                if (n0 + bnq[r] < N)
                    pb[r] = *(const float4*)&W[(size_t)(k0+bk[r])*N + n0 + bnq[r]];
                else { pb[r].x=pb[r].y=pb[r].z=pb[r].w=0.f; }
            }
        }
        const float* As_ = As + (ks&1)*GSTG;
        const float* Bs_ = Bs + (ks&1)*GSTG;
#pragma unroll
        for (int k8 = 0; k8 < 4; k8++) {
            unsigned a[4][4];
#pragma unroll
            for (int mt=0; mt<4; mt++) {
                int rb = wm*64 + mt*16;
                uint2 p0 = *(const uint2*)&As_[(rb+g  )*GASTR + k8*8 + 2*tg];
                uint2 p1 = *(const uint2*)&As_[(rb+g+8)*GASTR + k8*8 + 2*tg];
                a[mt][0]=p0.x; a[mt][2]=p0.y; a[mt][1]=p1.x; a[mt][3]=p1.y;
            }
#pragma unroll
            for (int nt=0; nt<4; nt++) {
                uint2 bb = *(const uint2*)&Bs_[(wn*32+nt*8+g)*GASTR + k8*8 + 2*tg];
                unsigned b[2] = {bb.x, bb.y};
#pragma unroll
                for (int mt=0; mt<4; mt++) mma8(acc[mt][nt], a[mt], b);
            }
        }
        if (ks < 31) {
            int st = ((ks+1)&1)*GSTG;
#pragma unroll
            for (int r=0; r<4; r++) {
                float* ap = &As[st + arow[r]*GASTR];
                ap[pk8(akq[r]+0)] = __uint_as_float(f2tf(pa[r].x));
                ap[pk8(akq[r]+1)] = __uint_as_float(f2tf(pa[r].y));
                ap[pk8(akq[r]+2)] = __uint_as_float(f2tf(pa[r].z));
                ap[pk8(akq[r]+3)] = __uint_as_float(f2tf(pa[r].w));
                int pc = pk8(bk[r]);
                Bs[st + (bnq[r]+0)*GASTR + pc] = __uint_as_float(f2tf(pb[r].x));
                Bs[st + (bnq[r]+1)*GASTR + pc] = __uint_as_float(f2tf(pb[r].y));
                Bs[st + (bnq[r]+2)*GASTR + pc] = __uint_as_float(f2tf(pb[r].z));
                Bs[st + (bnq[r]+3)*GASTR + pc] = __uint_as_float(f2tf(pb[r].w));
            }
        }
        __syncthreads();
    }

#pragma unroll
    for (int mt=0; mt<4; mt++) {
#pragma unroll
        for (int nt=0; nt<4; nt++) {
#pragma unroll
            for (int r=0; r<4; r++) {
                int m = m0 + wm*64 + mt*16 + g + ((r>>1)<<3);
                int n = n0 + wn*32 + nt*8 + 2*tg + (r&1);
                if (n >= N) continue;
                float c = acc[mt][nt][r] + bias[n];
                if (mode == MODE_Q || mode == MODE_K) {
                    float p = (c > 0.f) ? (c + 1.f) : expf(c);
                    int b = m >> 10, t = m & (NT-1);
                    int h = n >> 6,  d = n & 63;
                    float* dst = (mode == MODE_Q) ? g_Qp : g_Kp;
                    dst[((b*NH + h)*NT + t)*HD + d] = __uint_as_float(f2tf(p));
                } else if (mode == MODE_V) {
                    int b = m >> 10, t = m & (NT-1);
                    int h = n >> 6,  d = n & 63;
                    g_V[((b*NH + h)*NT + t)*HD + d] = __uint_as_float(f2tf(c));
                } else if (mode == MODE_L) {
                    g_logits[m*NHL + n] = c;
                } else { /* MODE_O */
                    outp[m*NHD + n] = c;
                }
            }
        }
    }
}

/* =====================================================================
 *  Softmax over L=12 per (b,h,t)
 * ===================================================================== */
__global__ void softmax_kernel()
{
    int id = blockIdx.x*blockDim.x + threadIdx.x;
    if (id >= NM*NH) return;
    int m = id / NH, h = id % NH;
    const float* lg = &g_logits[m*NHL + h*NL];
    float mx = lg[0];
#pragma unroll
    for (int l=1; l<NL; l++) mx = fmaxf(mx, lg[l]);
    float e[NL], s = 0.f;
#pragma unroll
    for (int l=0; l<NL; l++) { e[l] = expf(lg[l]-mx); s += e[l]; }
    float inv = 1.f/s;
    int b = m >> 10, t = m & (NT-1);
    float* wp = &g_w[((b*NH + h)*NT + t)*NL];
#pragma unroll
    for (int l=0; l<NL; l++) wp[l] = e[l]*inv;
}

/* =====================================================================
 *  Attention (tf32 mma), PAIR-BALANCED:
 *  block = (pair p, bh); processes qt=p then qt=7-p  => 9 key tiles each
 * ===================================================================== */
#define AQSTR 68
#define AJSTR 132
#define A_QS (128*AQSTR)
#define A_KS (128*AQSTR)
#define A_VS (64*AJSTR)
#define A_SS (128*AJSTR)
#define A_WS (128*NL)
#define ATTN_SMEM ((A_QS + A_KS + A_VS + A_SS + A_WS + 128)*4)

__global__ void __launch_bounds__(256,1)
attn_tc()
{
    extern __shared__ float sm[];
    float* Qs  = sm;
    float* Ks  = Qs  + A_QS;
    float* Vst = Ks  + A_KS;
    float* Ssm = Vst + A_VS;
    float* Ws  = Ssm + A_SS;
    float* den = Ws  + A_WS;

    const int tid = threadIdx.x;
    const int wid = tid>>5, lane = tid&31, g = lane>>2, tg = lane&3;
    const int wm = wid>>1, wn = wid&1;
    const int bh = blockIdx.y;
    const int pid = blockIdx.x;          /* 0..3 */

    const float* __restrict__ Qg = g_Qp + (size_t)bh*NT*HD;
    const float* __restrict__ Kg = g_Kp + (size_t)bh*NT*HD;
    const float* __restrict__ Vg = g_V  + (size_t)bh*NT*HD;
    const float* __restrict__ wg = g_w  + (size_t)bh*NT*NL;
    const int b = bh >> 4, h = bh & 15;

    for (int sel = 0; sel < 2; sel++) {
        const int qt = sel ? (7 - pid) : pid;
        const int i0 = qt*128;

        __syncthreads();   /* protect smem reuse across sel iterations */

        /* Q tile + level weights + den init */
#pragma unroll
        for (int r=0; r<8; r++) {
            int fid = r*256 + tid;
            int q = fid>>4, dq = (fid&15)<<2;
            float4 v = *(const float4*)&Qg[(size_t)(i0+q)*HD + dq];
            float* qp = &Qs[q*AQSTR];
            qp[pk8(dq+0)] = v.x; qp[pk8(dq+1)] = v.y;
            qp[pk8(dq+2)] = v.z; qp[pk8(dq+3)] = v.w;
        }
#pragma unroll
        for (int r=0; r<6; r++) { int fid = r*256+tid; Ws[fid] = wg[i0*NL + fid]; }
        if (tid < 128) den[tid] = 0.f;

        float oacc[2][4][4];
#pragma unroll
        for (int mt=0; mt<2; mt++)
#pragma unroll
            for (int nt=0; nt<4; nt++)
#pragma unroll
                for (int r=0; r<4; r++) oacc[mt][nt][r] = 0.f;

        const int ntiles = qt + 1;
        for (int jt = 0; jt < ntiles; jt++) {
            const int j0g = jt*128;
            __syncthreads();
#pragma unroll
            for (int r=0; r<8; r++) {
                int fid = r*256 + tid;
                int j = fid>>4, dq = (fid&15)<<2;
                float4 kv = *(const float4*)&Kg[(size_t)(j0g+j)*HD + dq];
                float* kp = &Ks[j*AQSTR];
                kp[pk8(dq+0)] = kv.x; kp[pk8(dq+1)] = kv.y;
                kp[pk8(dq+2)] = kv.z; kp[pk8(dq+3)] = kv.w;
                float4 vv = *(const float4*)&Vg[(size_t)(j0g+j)*HD + dq];
                int pj = pk8(j);
                Vst[(dq+0)*AJSTR + pj] = vv.x;
                Vst[(dq+1)*AJSTR + pj] = vv.y;
                Vst[(dq+2)*AJSTR + pj] = vv.z;
                Vst[(dq+3)*AJSTR + pj] = vv.w;
            }
            __syncthreads();

            /* S = Q K^T : warp tile 32x64 */
            float sacc[2][8][4];
#pragma unroll
            for (int mt=0; mt<2; mt++)
#pragma unroll
                for (int nt=0; nt<8; nt++)
#pragma unroll
                    for (int r=0; r<4; r++) sacc[mt][nt][r] = 0.f;

#pragma unroll
            for (int k8=0; k8<8; k8++) {
                unsigned a[2][4];
#pragma unroll
                for (int mt=0; mt<2; mt++) {
                    int rb = wm*32 + mt*16;
                    uint2 p0 = *(const uint2*)&Qs[(rb+g  )*AQSTR + k8*8 + 2*tg];
                    uint2 p1 = *(const uint2*)&Qs[(rb+g+8)*AQSTR + k8*8 + 2*tg];
                    a[mt][0]=p0.x; a[mt][2]=p0.y; a[mt][1]=p1.x; a[mt][3]=p1.y;
                }
#pragma unroll
                for (int nt=0; nt<8; nt++) {
                    uint2 bb = *(const uint2*)&Ks[(wn*64+nt*8+g)*AQSTR + k8*8 + 2*tg];
                    unsigned bfr[2] = {bb.x, bb.y};
                    mma8(sacc[0][nt], a[0], bfr);
                    mma8(sacc[1][nt], a[1], bfr);
                }
            }

            /* weight + mask + store Ssm + row sums */
            float rs[2][2] = {{0.f,0.f},{0.f,0.f}};
#pragma unroll
            for (int mt=0; mt<2; mt++) {
#pragma unroll
                for (int nt=0; nt<8; nt++) {
#pragma unroll
                    for (int r=0; r<4; r++) {
                        int il = wm*32 + mt*16 + g + ((r>>1)<<3);
                        int jl = wn*64 + nt*8 + 2*tg + (r&1);
                        int i = i0 + il, j = j0g + jl;
                        float v = 0.f;
                        if (j <= i) {
                            int lev = 31 - __clz(j ^ (i+1));
                            v = sacc[mt][nt][r] * Ws[il*NL + lev];
                        }
                        rs[mt][r>>1] += v;
                        Ssm[il*AJSTR + pk8(jl)] = __uint_as_float(f2tf(v));
                    }
                }
            }
#pragma unroll
            for (int mt=0; mt<2; mt++) {
#pragma unroll
                for (int hf=0; hf<2; hf++) {
                    float v = rs[mt][hf];
                    v += __shfl_xor_sync(0xFFFFFFFFu, v, 1);
                    v += __shfl_xor_sync(0xFFFFFFFFu, v, 2);
                    if (tg == 0)
                        atomicAdd(&den[wm*32 + mt*16 + g + hf*8], v);
                }
            }
            __syncthreads();

            /* O += Ssm @ V : warp tile 32x32 */
#pragma unroll
            for (int k8=0; k8<16; k8++) {
                unsigned a[2][4];
#pragma unroll
                for (int mt=0; mt<2; mt++) {
                    int rb = wm*32 + mt*16;
                    uint2 p0 = *(const uint2*)&Ssm[(rb+g  )*AJSTR + k8*8 + 2*tg];
                    uint2 p1 = *(const uint2*)&Ssm[(rb+g+8)*AJSTR + k8*8 + 2*tg];
                    a[mt][0]=p0.x; a[mt][2]=p0.y; a[mt][1]=p1.x; a[mt][3]=p1.y;
                }
#pragma unroll
                for (int nt=0; nt<4; nt++) {
                    uint2 bb = *(const uint2*)&Vst[(wn*32+nt*8+g)*AJSTR + k8*8 + 2*tg];
                    unsigned bfr[2] = {bb.x, bb.y};
                    mma8(oacc[0][nt], a[0], bfr);
                    mma8(oacc[1][nt], a[1], bfr);
                }
            }
        }

        __syncthreads();   /* den atomics complete */

        float rcp[2][2];
#pragma unroll
        for (int mt=0; mt<2; mt++)
#pragma unroll
            for (int hf=0; hf<2; hf++)
                rcp[mt][hf] = 1.f / fmaxf(den[wm*32 + mt*16 + g + hf*8], 1e-6f);
#pragma unroll
        for (int mt=0; mt<2; mt++) {
#pragma unroll
            for (int nt=0; nt<4; nt++) {
#pragma unroll
                for (int r=0; r<4; r++) {
                    int il = wm*32 + mt*16 + g + ((r>>1)<<3);
                    int e  = wn*32 + nt*8 + 2*tg + (r&1);
                    g_attn[(size_t)(b*NT + i0 + il)*NHD + h*HD + e] =
                        oacc[mt][nt][r] * rcp[mt][r>>1];
                }
            }
        }
    }
}

/* ===================================================================== */
extern "C" void kernel_launch(void* const* d_in, const int* in_sizes, int n_in,
                              void* d_out, int out_size)
{
    const float* x  = (const float*)d_in[0];
    const float* qw = (const float*)d_in[1];
    const float* qb = (const float*)d_in[2];
    const float* kw = (const float*)d_in[3];
    const float* kb = (const float*)d_in[4];
    const float* vw = (const float*)d_in[5];
    const float* vb = (const float*)d_in[6];
    const float* lw = (const float*)d_in[7];
    const float* lb = (const float*)d_in[8];
    const float* ow = (const float*)d_in[9];
    const float* ob = (const float*)d_in[10];
    float* out = (float*)d_out;

    cudaFuncSetAttribute(gemm_tc, cudaFuncAttributeMaxDynamicSharedMemorySize, GEMM_SMEM);
    cudaFuncSetAttribute(attn_tc, cudaFuncAttributeMaxDynamicSharedMemorySize, ATTN_SMEM);

    /* fused Q/K/V/L projections (z selects weight & mode) */
    gemm_tc<<<dim3(8,16,4), 256, GEMM_SMEM>>>(x, qw, kw, vw, lw, qb, kb, vb, lb,
                                              nullptr, NHD, MODE_Q);
    softmax_kernel<<<(NM*NH + 255)/256, 256>>>();
    attn_tc<<<dim3(4, NB*NH), 256, ATTN_SMEM>>>();
    /* output projection */
    gemm_tc<<<dim3(8,16,1), 256, GEMM_SMEM>>>(nullptr, ow, ow, ow, ow, ob, ob, ob, ob,
                                              out, NHD, MODE_O);
}

// round 6
// speedup vs baseline: 2.2467x; 1.1801x over previous
#include <cuda_runtime.h>
#include <math.h>

#define NB 2
#define NT 1024
#define NH 16
#define HD 64
#define NL 12
#define NM (NB*NT)        /* 2048 */
#define NHL (NH*NL)       /* 192  */
#define NHD (NH*HD)       /* 1024 */

/* ---------------- scratch ---------------- */
__device__ float g_Qp[NB*NH*NT*HD];
__device__ float g_Kp[NB*NH*NT*HD];
__device__ float g_V [NB*NH*NT*HD];
__device__ float g_logits[NM*NHL];
__device__ float g_w[NB*NH*NT*NL];
__device__ float g_attn[NM*NHD];

/* ---------------- helpers ---------------- */
__device__ __forceinline__ unsigned f2tf(float f){
    unsigned u; asm("cvt.rna.tf32.f32 %0, %1;" : "=r"(u) : "f"(f)); return u;
}
__device__ __forceinline__ void mma8(float* c, const unsigned* a, const unsigned* b){
    asm volatile("mma.sync.aligned.m16n8k8.row.col.f32.tf32.tf32.f32 "
        "{%0,%1,%2,%3}, {%4,%5,%6,%7}, {%8,%9}, {%0,%1,%2,%3};"
        : "+f"(c[0]),"+f"(c[1]),"+f"(c[2]),"+f"(c[3])
        : "r"(a[0]),"r"(a[1]),"r"(a[2]),"r"(a[3]),"r"(b[0]),"r"(b[1]));
}
__device__ __forceinline__ int pk8(int c){ return (c & ~7) | ((c&3)<<1) | ((c>>2)&1); }

enum { MODE_Q = 0, MODE_K = 1, MODE_V = 2, MODE_L = 3, MODE_O = 4 };

/* =====================================================================
 *  tf32 tensor-core GEMM: C[M=2048, N] = A[M,1024] @ W[1024,N] + bias
 *  128x128x32 tile, double-buffered, 16 warps, warp tile 32x32
 * ===================================================================== */
#define GASTR 36
#define GSTG (128*GASTR)
#define GEMM_SMEM (4*GSTG*4)

__global__ void __launch_bounds__(512,1)
gemm_tc(const float* __restrict__ A_in,
        const float* __restrict__ W0, const float* __restrict__ W1,
        const float* __restrict__ W2, const float* __restrict__ W3,
        const float* __restrict__ Bi0, const float* __restrict__ Bi1,
        const float* __restrict__ Bi2, const float* __restrict__ Bi3,
        float* __restrict__ outp, int Npar, int mode0)
{
    extern __shared__ float sm[];
    float* As = sm;
    float* Bs = sm + 2*GSTG;

    const int z = blockIdx.z;
    const int mode = mode0 + z;
    const int N = (mode == MODE_L) ? NHL : Npar;
    const int n0 = blockIdx.x*128;
    if (n0 >= N) return;
    const float* __restrict__ W    = (z==0)?W0 :(z==1)?W1 :(z==2)?W2 :W3;
    const float* __restrict__ bias = (z==0)?Bi0:(z==1)?Bi1:(z==2)?Bi2:Bi3;
    const float* __restrict__ A = (mode==MODE_O) ? g_attn : A_in;

    const int tid = threadIdx.x;
    const int m0 = blockIdx.y*128;
    const int wid = tid>>5, lane = tid&31, g = lane>>2, tg = lane&3;
    const int wm = wid>>2, wn = wid&3;           /* 4x4 warps, tile 32x32 */

    float acc[2][4][4];
#pragma unroll
    for (int mt=0; mt<2; mt++)
#pragma unroll
        for (int nt=0; nt<4; nt++)
#pragma unroll
            for (int r=0; r<4; r++) acc[mt][nt][r] = 0.f;

    int arow[2], akq[2], bk[2], bnq[2];
#pragma unroll
    for (int r=0; r<2; r++) {
        int fid = r*512 + tid;
        arow[r] = fid>>3;  akq[r] = (fid&7)<<2;   /* 128 rows x 8 float4 */
        bk[r]   = fid>>5;  bnq[r] = (fid&31)<<2;  /* 32 k x 32 float4    */
    }

    float4 pa[2], pb[2];
#pragma unroll
    for (int r=0; r<2; r++) {
        pa[r] = *(const float4*)&A[(size_t)(m0+arow[r])*1024 + akq[r]];
        if (n0 + bnq[r] < N)
            pb[r] = *(const float4*)&W[(size_t)bk[r]*N + n0 + bnq[r]];
        else { pb[r].x=pb[r].y=pb[r].z=pb[r].w=0.f; }
    }
#pragma unroll
    for (int r=0; r<2; r++) {
        float* ap = &As[arow[r]*GASTR];
        ap[pk8(akq[r]+0)] = __uint_as_float(f2tf(pa[r].x));
        ap[pk8(akq[r]+1)] = __uint_as_float(f2tf(pa[r].y));
        ap[pk8(akq[r]+2)] = __uint_as_float(f2tf(pa[r].z));
        ap[pk8(akq[r]+3)] = __uint_as_float(f2tf(pa[r].w));
        int pc = pk8(bk[r]);
        Bs[(bnq[r]+0)*GASTR + pc] = __uint_as_float(f2tf(pb[r].x));
        Bs[(bnq[r]+1)*GASTR + pc] = __uint_as_float(f2tf(pb[r].y));
        Bs[(bnq[r]+2)*GASTR + pc] = __uint_as_float(f2tf(pb[r].z));
        Bs[(bnq[r]+3)*GASTR + pc] = __uint_as_float(f2tf(pb[r].w));
    }
    __syncthreads();

    for (int ks = 0; ks < 32; ks++) {
        if (ks < 31) {
            int k0 = (ks+1)*32;
#pragma unroll
            for (int r=0; r<2; r++) {
                pa[r] = *(const float4*)&A[(size_t)(m0+arow[r])*1024 + k0 + akq[r]];
                if (n0 + bnq[r] < N)
                    pb[r] = *(const float4*)&W[(size_t)(k0+bk[r])*N + n0 + bnq[r]];
                else { pb[r].x=pb[r].y=pb[r].z=pb[r].w=0.f; }
            }
        }
        const float* As_ = As + (ks&1)*GSTG;
        const float* Bs_ = Bs + (ks&1)*GSTG;
#pragma unroll
        for (int k8 = 0; k8 < 4; k8++) {
            unsigned a[2][4];
#pragma unroll
            for (int mt=0; mt<2; mt++) {
                int rb = wm*32 + mt*16;
                uint2 p0 = *(const uint2*)&As_[(rb+g  )*GASTR + k8*8 + 2*tg];
                uint2 p1 = *(const uint2*)&As_[(rb+g+8)*GASTR + k8*8 + 2*tg];
                a[mt][0]=p0.x; a[mt][2]=p0.y; a[mt][1]=p1.x; a[mt][3]=p1.y;
            }
#pragma unroll
            for (int nt=0; nt<4; nt++) {
                uint2 bb = *(const uint2*)&Bs_[(wn*32+nt*8+g)*GASTR + k8*8 + 2*tg];
                unsigned b[2] = {bb.x, bb.y};
                mma8(acc[0][nt], a[0], b);
                mma8(acc[1][nt], a[1], b);
            }
        }
        if (ks < 31) {
            int st = ((ks+1)&1)*GSTG;
#pragma unroll
            for (int r=0; r<2; r++) {
                float* ap = &As[st + arow[r]*GASTR];
                ap[pk8(akq[r]+0)] = __uint_as_float(f2tf(pa[r].x));
                ap[pk8(akq[r]+1)] = __uint_as_float(f2tf(pa[r].y));
                ap[pk8(akq[r]+2)] = __uint_as_float(f2tf(pa[r].z));
                ap[pk8(akq[r]+3)] = __uint_as_float(f2tf(pa[r].w));
                int pc = pk8(bk[r]);
                Bs[st + (bnq[r]+0)*GASTR + pc] = __uint_as_float(f2tf(pb[r].x));
                Bs[st + (bnq[r]+1)*GASTR + pc] = __uint_as_float(f2tf(pb[r].y));
                Bs[st + (bnq[r]+2)*GASTR + pc] = __uint_as_float(f2tf(pb[r].z));
                Bs[st + (bnq[r]+3)*GASTR + pc] = __uint_as_float(f2tf(pb[r].w));
            }
        }
        __syncthreads();
    }

#pragma unroll
    for (int mt=0; mt<2; mt++) {
#pragma unroll
        for (int nt=0; nt<4; nt++) {
#pragma unroll
            for (int r=0; r<4; r++) {
                int m = m0 + wm*32 + mt*16 + g + ((r>>1)<<3);
                int n = n0 + wn*32 + nt*8 + 2*tg + (r&1);
                if (n >= N) continue;
                float c = acc[mt][nt][r] + bias[n];
                if (mode == MODE_Q || mode == MODE_K) {
                    float p = (c > 0.f) ? (c + 1.f) : expf(c);
                    int b = m >> 10, t = m & (NT-1);
                    int h = n >> 6,  d = n & 63;
                    float* dst = (mode == MODE_Q) ? g_Qp : g_Kp;
                    dst[((b*NH + h)*NT + t)*HD + d] = __uint_as_float(f2tf(p));
                } else if (mode == MODE_V) {
                    int b = m >> 10, t = m & (NT-1);
                    int h = n >> 6,  d = n & 63;
                    g_V[((b*NH + h)*NT + t)*HD + d] = __uint_as_float(f2tf(c));
                } else if (mode == MODE_L) {
                    g_logits[m*NHL + n] = c;
                } else { /* MODE_O */
                    outp[m*NHD + n] = c;
                }
            }
        }
    }
}

/* =====================================================================
 *  Softmax over L=12 per (b,h,t)
 * ===================================================================== */
__global__ void softmax_kernel()
{
    int id = blockIdx.x*blockDim.x + threadIdx.x;
    if (id >= NM*NH) return;
    int m = id / NH, h = id % NH;
    const float* lg = &g_logits[m*NHL + h*NL];
    float mx = lg[0];
#pragma unroll
    for (int l=1; l<NL; l++) mx = fmaxf(mx, lg[l]);
    float e[NL], s = 0.f;
#pragma unroll
    for (int l=0; l<NL; l++) { e[l] = expf(lg[l]-mx); s += e[l]; }
    float inv = 1.f/s;
    int b = m >> 10, t = m & (NT-1);
    float* wp = &g_w[((b*NH + h)*NT + t)*NL];
#pragma unroll
    for (int l=0; l<NL; l++) wp[l] = e[l]*inv;
}

/* =====================================================================
 *  Attention (tf32 mma), pair-balanced, 512 threads (16 warps)
 *  warp grid 4x4: S warp tile 32x32, O warp tile 32x16
 * ===================================================================== */
#define AQSTR 68
#define AJSTR 132
#define A_QS (128*AQSTR)
#define A_KS (128*AQSTR)
#define A_VS (64*AJSTR)
#define A_SS (128*AJSTR)
#define A_WS (128*NL)
#define ATTN_SMEM ((A_QS + A_KS + A_VS + A_SS + A_WS + 128)*4)

__global__ void __launch_bounds__(512,1)
attn_tc()
{
    extern __shared__ float sm[];
    float* Qs  = sm;
    float* Ks  = Qs  + A_QS;
    float* Vst = Ks  + A_KS;
    float* Ssm = Vst + A_VS;
    float* Ws  = Ssm + A_SS;
    float* den = Ws  + A_WS;

    const int tid = threadIdx.x;
    const int wid = tid>>5, lane = tid&31, g = lane>>2, tg = lane&3;
    const int wm = wid>>2, wn = wid&3;      /* 4x4 warps */
    const int bh = blockIdx.y;
    const int pid = blockIdx.x;             /* 0..3 */

    const float* __restrict__ Qg = g_Qp + (size_t)bh*NT*HD;
    const float* __restrict__ Kg = g_Kp + (size_t)bh*NT*HD;
    const float* __restrict__ Vg = g_V  + (size_t)bh*NT*HD;
    const float* __restrict__ wg = g_w  + (size_t)bh*NT*NL;
    const int b = bh >> 4, h = bh & 15;

    for (int sel = 0; sel < 2; sel++) {
        const int qt = sel ? (7 - pid) : pid;
        const int i0 = qt*128;

        __syncthreads();

        /* Q tile + level weights + den init */
#pragma unroll
        for (int r=0; r<4; r++) {
            int fid = r*512 + tid;              /* 0..2047 */
            int q = fid>>4, dq = (fid&15)<<2;
            float4 v = *(const float4*)&Qg[(size_t)(i0+q)*HD + dq];
            float* qp = &Qs[q*AQSTR];
            qp[pk8(dq+0)] = v.x; qp[pk8(dq+1)] = v.y;
            qp[pk8(dq+2)] = v.z; qp[pk8(dq+3)] = v.w;
        }
#pragma unroll
        for (int r=0; r<3; r++) { int fid = r*512+tid; Ws[fid] = wg[i0*NL + fid]; }
        if (tid < 128) den[tid] = 0.f;

        float oacc[2][2][4];
#pragma unroll
        for (int mt=0; mt<2; mt++)
#pragma unroll
            for (int nt=0; nt<2; nt++)
#pragma unroll
                for (int r=0; r<4; r++) oacc[mt][nt][r] = 0.f;

        const int ntiles = qt + 1;
        for (int jt = 0; jt < ntiles; jt++) {
            const int j0g = jt*128;
            __syncthreads();
#pragma unroll
            for (int r=0; r<4; r++) {
                int fid = r*512 + tid;
                int j = fid>>4, dq = (fid&15)<<2;
                float4 kv = *(const float4*)&Kg[(size_t)(j0g+j)*HD + dq];
                float* kp = &Ks[j*AQSTR];
                kp[pk8(dq+0)] = kv.x; kp[pk8(dq+1)] = kv.y;
                kp[pk8(dq+2)] = kv.z; kp[pk8(dq+3)] = kv.w;
                float4 vv = *(const float4*)&Vg[(size_t)(j0g+j)*HD + dq];
                int pj = pk8(j);
                Vst[(dq+0)*AJSTR + pj] = vv.x;
                Vst[(dq+1)*AJSTR + pj] = vv.y;
                Vst[(dq+2)*AJSTR + pj] = vv.z;
                Vst[(dq+3)*AJSTR + pj] = vv.w;
            }
            __syncthreads();

            /* S = Q K^T : warp tile 32x32 */
            float sacc[2][4][4];
#pragma unroll
            for (int mt=0; mt<2; mt++)
#pragma unroll
                for (int nt=0; nt<4; nt++)
#pragma unroll
                    for (int r=0; r<4; r++) sacc[mt][nt][r] = 0.f;

#pragma unroll
            for (int k8=0; k8<8; k8++) {
                unsigned a[2][4];
#pragma unroll
                for (int mt=0; mt<2; mt++) {
                    int rb = wm*32 + mt*16;
                    uint2 p0 = *(const uint2*)&Qs[(rb+g  )*AQSTR + k8*8 + 2*tg];
                    uint2 p1 = *(const uint2*)&Qs[(rb+g+8)*AQSTR + k8*8 + 2*tg];
                    a[mt][0]=p0.x; a[mt][2]=p0.y; a[mt][1]=p1.x; a[mt][3]=p1.y;
                }
#pragma unroll
                for (int nt=0; nt<4; nt++) {
                    uint2 bb = *(const uint2*)&Ks[(wn*32+nt*8+g)*AQSTR + k8*8 + 2*tg];
                    unsigned bfr[2] = {bb.x, bb.y};
                    mma8(sacc[0][nt], a[0], bfr);
                    mma8(sacc[1][nt], a[1], bfr);
                }
            }

            /* weight + mask + store Ssm + row sums */
            float rs[2][2] = {{0.f,0.f},{0.f,0.f}};
#pragma unroll
            for (int mt=0; mt<2; mt++) {
#pragma unroll
                for (int nt=0; nt<4; nt++) {
#pragma unroll
                    for (int r=0; r<4; r++) {
                        int il = wm*32 + mt*16 + g + ((r>>1)<<3);
                        int jl = wn*32 + nt*8 + 2*tg + (r&1);
                        int i = i0 + il, j = j0g + jl;
                        float v = 0.f;
                        if (j <= i) {
                            int lev = 31 - __clz(j ^ (i+1));
                            v = sacc[mt][nt][r] * Ws[il*NL + lev];
                        }
                        rs[mt][r>>1] += v;
                        Ssm[il*AJSTR + pk8(jl)] = __uint_as_float(f2tf(v));
                    }
                }
            }
#pragma unroll
            for (int mt=0; mt<2; mt++) {
#pragma unroll
                for (int hf=0; hf<2; hf++) {
                    float v = rs[mt][hf];
                    v += __shfl_xor_sync(0xFFFFFFFFu, v, 1);
                    v += __shfl_xor_sync(0xFFFFFFFFu, v, 2);
                    if (tg == 0)
                        atomicAdd(&den[wm*32 + mt*16 + g + hf*8], v);
                }
            }
            __syncthreads();

            /* O += Ssm @ V : warp tile 32x16 */
#pragma unroll
            for (int k8=0; k8<16; k8++) {
                unsigned a[2][4];
#pragma unroll
                for (int mt=0; mt<2; mt++) {
                    int rb = wm*32 + mt*16;
                    uint2 p0 = *(const uint2*)&Ssm[(rb+g  )*AJSTR + k8*8 + 2*tg];
                    uint2 p1 = *(const uint2*)&Ssm[(rb+g+8)*AJSTR + k8*8 + 2*tg];
                    a[mt][0]=p0.x; a[mt][2]=p0.y; a[mt][1]=p1.x; a[mt][3]=p1.y;
                }
#pragma unroll
                for (int nt=0; nt<2; nt++) {
                    uint2 bb = *(const uint2*)&Vst[(wn*16+nt*8+g)*AJSTR + k8*8 + 2*tg];
                    unsigned bfr[2] = {bb.x, bb.y};
                    mma8(oacc[0][nt], a[0], bfr);
                    mma8(oacc[1][nt], a[1], bfr);
                }
            }
        }

        __syncthreads();   /* den atomics complete */

        float rcp[2][2];
#pragma unroll
        for (int mt=0; mt<2; mt++)
#pragma unroll
            for (int hf=0; hf<2; hf++)
                rcp[mt][hf] = 1.f / fmaxf(den[wm*32 + mt*16 + g + hf*8], 1e-6f);
#pragma unroll
        for (int mt=0; mt<2; mt++) {
#pragma unroll
            for (int nt=0; nt<2; nt++) {
#pragma unroll
                for (int r=0; r<4; r++) {
                    int il = wm*32 + mt*16 + g + ((r>>1)<<3);
                    int e  = wn*16 + nt*8 + 2*tg + (r&1);
                    g_attn[(size_t)(b*NT + i0 + il)*NHD + h*HD + e] =
                        oacc[mt][nt][r] * rcp[mt][r>>1];
                }
            }
        }
    }
}

/* ===================================================================== */
extern "C" void kernel_launch(void* const* d_in, const int* in_sizes, int n_in,
                              void* d_out, int out_size)
{
    const float* x  = (const float*)d_in[0];
    const float* qw = (const float*)d_in[1];
    const float* qb = (const float*)d_in[2];
    const float* kw = (const float*)d_in[3];
    const float* kb = (const float*)d_in[4];
    const float* vw = (const float*)d_in[5];
    const float* vb = (const float*)d_in[6];
    const float* lw = (const float*)d_in[7];
    const float* lb = (const float*)d_in[8];
    const float* ow = (const float*)d_in[9];
    const float* ob = (const float*)d_in[10];
    float* out = (float*)d_out;

    cudaFuncSetAttribute(gemm_tc, cudaFuncAttributeMaxDynamicSharedMemorySize, GEMM_SMEM);
    cudaFuncSetAttribute(attn_tc, cudaFuncAttributeMaxDynamicSharedMemorySize, ATTN_SMEM);

    gemm_tc<<<dim3(8,16,4), 512, GEMM_SMEM>>>(x, qw, kw, vw, lw, qb, kb, vb, lb,
                                              nullptr, NHD, MODE_Q);
    softmax_kernel<<<(NM*NH + 255)/256, 256>>>();
    attn_tc<<<dim3(4, NB*NH), 512, ATTN_SMEM>>>();
    gemm_tc<<<dim3(8,16,1), 512, GEMM_SMEM>>>(nullptr, ow, ow, ow, ow, ob, ob, ob, ob,
                                              out, NHD, MODE_O);
}

// round 11
// speedup vs baseline: 3.9611x; 1.7631x over previous
#include <cuda_runtime.h>
#include <math.h>
#include <stdint.h>

#define NB 2
#define NT 1024
#define NH 16
#define HD 64
#define NL 12
#define NM (NB*NT)        /* 2048 */
#define NHL (NH*NL)       /* 192  */
#define NHD (NH*HD)       /* 1024 */

/* ---------------- scratch ---------------- */
__device__ float g_Qp[NB*NH*NT*HD];     /* tf32-rounded phi(Q) [B,H,T,D] */
__device__ float g_Kp[NB*NH*NT*HD];
__device__ float g_V [NB*NH*NT*HD];
__device__ float g_logits[NM*NHL];
__device__ float g_w[NB*NH*NT*NL];
__device__ float g_attn[NM*NHD];        /* tf32-rounded head outputs */
/* tf32 pre-rounded inputs */
__device__ float g_xT [NM*1024];
__device__ float g_qwT[1024*NHD];
__device__ float g_kwT[1024*NHD];
__device__ float g_vwT[1024*NHD];
__device__ float g_lwT[1024*NHL];
__device__ float g_owT[NHD*1024];

/* ---------------- helpers ---------------- */
__device__ __forceinline__ unsigned f2tf(float f){
    unsigned u; asm("cvt.rna.tf32.f32 %0, %1;" : "=r"(u) : "f"(f)); return u;
}
__device__ __forceinline__ void mma8(float* c, const unsigned* a, const unsigned* b){
    asm volatile("mma.sync.aligned.m16n8k8.row.col.f32.tf32.tf32.f32 "
        "{%0,%1,%2,%3}, {%4,%5,%6,%7}, {%8,%9}, {%0,%1,%2,%3};"
        : "+f"(c[0]),"+f"(c[1]),"+f"(c[2]),"+f"(c[3])
        : "r"(a[0]),"r"(a[1]),"r"(a[2]),"r"(a[3]),"r"(b[0]),"r"(b[1]));
}
__device__ __forceinline__ int pk8(int c){ return (c & ~7) | ((c&3)<<1) | ((c>>2)&1); }
__device__ __forceinline__ uint32_t s2u(const void* p){
    uint32_t a;
    asm("{ .reg .u64 t; cvta.to.shared.u64 t, %1; cvt.u32.u64 %0, t; }" : "=r"(a) : "l"(p));
    return a;
}
__device__ __forceinline__ void cpa16(uint32_t dst, const void* src){
    asm volatile("cp.async.cg.shared.global [%0], [%1], 16;" :: "r"(dst), "l"(src) : "memory");
}
__device__ __forceinline__ void cpa_commit(){
    asm volatile("cp.async.commit_group;" ::: "memory");
}
__device__ __forceinline__ void cpa_wait0(){
    asm volatile("cp.async.wait_group 0;" ::: "memory");
}
__device__ __forceinline__ void cpa_wait1(){
    asm volatile("cp.async.wait_group 1;" ::: "memory");
}

enum { MODE_Q = 0, MODE_K = 1, MODE_V = 2, MODE_L = 3, MODE_O = 4 };

/* =====================================================================
 *  Prepass: round inputs to tf32 (float4 pass)
 * ===================================================================== */
#define CV0 524288
#define CV1 786432
#define CV2 1048576
#define CV3 1310720
#define CV4 1359872
#define CV5 1622016
__global__ void cvt_kernel(const float4* __restrict__ x,  const float4* __restrict__ qw,
                           const float4* __restrict__ kw, const float4* __restrict__ vw,
                           const float4* __restrict__ lw, const float4* __restrict__ ow)
{
    int id = blockIdx.x*blockDim.x + threadIdx.x;
    const float4* s; float4* d; int off;
    if      (id < CV0) { s=x;  d=(float4*)g_xT;  off=id; }
    else if (id < CV1) { s=qw; d=(float4*)g_qwT; off=id-CV0; }
    else if (id < CV2) { s=kw; d=(float4*)g_kwT; off=id-CV1; }
    else if (id < CV3) { s=vw; d=(float4*)g_vwT; off=id-CV2; }
    else if (id < CV4) { s=lw; d=(float4*)g_lwT; off=id-CV3; }
    else if (id < CV5) { s=ow; d=(float4*)g_owT; off=id-CV4; }
    else return;
    float4 v = s[off];
    v.x = __uint_as_float(f2tf(v.x));
    v.y = __uint_as_float(f2tf(v.y));
    v.z = __uint_as_float(f2tf(v.z));
    v.w = __uint_as_float(f2tf(v.w));
    d[off] = v;
}

/* =====================================================================
 *  tf32 mma.sync GEMM, cp.async staged, conflict-free strides
 *  C[2048,N] = A[2048,1024] @ W[1024,N] + bias
 *  128x128x32 tile, 3-stage ring, 512 thr, warp 32x32 (4x4 grid)
 *  A stage: [128 m][36] canonical (LDS.32 frags, bank g*4+tg, CF)
 *  B stage: [32 k][136] canonical (LDS.32 frags, bank tg*8+g, CF)
 * ===================================================================== */
#define GA_STR 36
#define GB_STR 136
#define GA_BYTES (128*GA_STR*4)     /* 18432 */
#define GB_BYTES (32*GB_STR*4)      /* 17408 */
#define GSTAGE   (GA_BYTES + GB_BYTES)
#define GEMM_SMEM (3*GSTAGE)        /* 107520 */

__global__ void __launch_bounds__(512,1)
gemm_tc(const float* __restrict__ Bi0, const float* __restrict__ Bi1,
        const float* __restrict__ Bi2, const float* __restrict__ Bi3,
        float* __restrict__ outp, int Npar, int mode0)
{
    extern __shared__ float sm[];
    const uint32_t sb = s2u(sm);

    const int z = blockIdx.z;
    const int mode = mode0 + z;
    const int N = (mode == MODE_L) ? NHL : Npar;
    const int n0 = blockIdx.x*128;
    if (n0 >= N) return;
    const int m0 = blockIdx.y*128;
    const float* __restrict__ bias = (z==0)?Bi0:(z==1)?Bi1:(z==2)?Bi2:Bi3;
    const float* __restrict__ W =
        (mode==MODE_Q)?g_qwT:(mode==MODE_K)?g_kwT:(mode==MODE_V)?g_vwT:
        (mode==MODE_L)?g_lwT:g_owT;
    const float* __restrict__ A = (mode==MODE_O) ? g_attn : g_xT;

    const int tid = threadIdx.x;
    const int wid = tid>>5, lane = tid&31, g = lane>>2, tg = lane&3;
    const int wm = wid>>2, wn = wid&3;

    float acc[2][4][4];
#pragma unroll
    for (int mt=0; mt<2; mt++)
#pragma unroll
        for (int nt=0; nt<4; nt++)
#pragma unroll
            for (int r=0; r<4; r++) acc[mt][nt][r] = 0.f;

    /* producer: chunk c -> stage st (async) */
    auto produce = [&](int c, int st){
        const int k0c = c*32;
        const uint32_t base = sb + st*GSTAGE;
#pragma unroll
        for (int p=0; p<2; p++) {
            int fid = p*512 + tid;
            int m = fid>>3, k4 = (fid&7)<<2;
            cpa16(base + (m*GA_STR + k4)*4, &A[(size_t)(m0+m)*1024 + k0c + k4]);
        }
#pragma unroll
        for (int p=0; p<2; p++) {
            int fid = p*512 + tid;
            int k = fid>>5, n4 = (fid&31)<<2;
            uint32_t dst = base + GA_BYTES + (k*GB_STR + n4)*4;
            if (n0 + n4 + 3 < N) {
                cpa16(dst, &W[(size_t)(k0c+k)*N + n0 + n4]);
            } else {
                float4 zz = {0.f,0.f,0.f,0.f};
                *(float4*)((char*)sm + (dst - sb)) = zz;
            }
        }
        cpa_commit();
    };

    produce(0, 0);
    produce(1, 1);

    for (int c = 0; c < 32; c++) {
        const int st = c % 3;
        if (c < 31) cpa_wait1(); else cpa_wait0();
        __syncthreads();
        if (c + 2 < 32) produce(c+2, (c+2)%3);

        const unsigned* Au = (const unsigned*)(sm + st*(GSTAGE/4));
        const unsigned* Bu = Au + GA_BYTES/4;
#pragma unroll
        for (int k8 = 0; k8 < 4; k8++) {
            unsigned a[2][4];
#pragma unroll
            for (int mt=0; mt<2; mt++) {
                int rb = wm*32 + mt*16;
                a[mt][0] = Au[(rb+g  )*GA_STR + k8*8 + tg];
                a[mt][1] = Au[(rb+g+8)*GA_STR + k8*8 + tg];
                a[mt][2] = Au[(rb+g  )*GA_STR + k8*8 + tg+4];
                a[mt][3] = Au[(rb+g+8)*GA_STR + k8*8 + tg+4];
            }
#pragma unroll
            for (int nt=0; nt<4; nt++) {
                int nc = wn*32 + nt*8 + g;
                unsigned b[2];
                b[0] = Bu[(k8*8+tg  )*GB_STR + nc];
                b[1] = Bu[(k8*8+tg+4)*GB_STR + nc];
                mma8(acc[0][nt], a[0], b);
                mma8(acc[1][nt], a[1], b);
            }
        }
    }

    /* epilogue */
#pragma unroll
    for (int mt=0; mt<2; mt++) {
#pragma unroll
        for (int nt=0; nt<4; nt++) {
#pragma unroll
            for (int r=0; r<4; r++) {
                int m = m0 + wm*32 + mt*16 + g + ((r>>1)<<3);
                int n = n0 + wn*32 + nt*8 + 2*tg + (r&1);
                if (n >= N) continue;
                float c = acc[mt][nt][r] + bias[n];
                if (mode == MODE_Q || mode == MODE_K) {
                    float p = (c > 0.f) ? (c + 1.f) : expf(c);
                    int b = m >> 10, t = m & (NT-1);
                    int h = n >> 6,  d = n & 63;
                    float* dst = (mode == MODE_Q) ? g_Qp : g_Kp;
                    dst[((b*NH + h)*NT + t)*HD + d] = __uint_as_float(f2tf(p));
                } else if (mode == MODE_V) {
                    int b = m >> 10, t = m & (NT-1);
                    int h = n >> 6,  d = n & 63;
                    g_V[((b*NH + h)*NT + t)*HD + d] = __uint_as_float(f2tf(c));
                } else if (mode == MODE_L) {
                    g_logits[m*NHL + n] = c;
                } else {
                    outp[m*NHD + n] = c;
                }
            }
        }
    }
}

/* =====================================================================
 *  Softmax over L=12 per (b,h,t)
 * ===================================================================== */
__global__ void softmax_kernel()
{
    int id = blockIdx.x*blockDim.x + threadIdx.x;
    if (id >= NM*NH) return;
    int m = id / NH, h = id % NH;
    const float* lg = &g_logits[m*NHL + h*NL];
    float mx = lg[0];
#pragma unroll
    for (int l=1; l<NL; l++) mx = fmaxf(mx, lg[l]);
    float e[NL], s = 0.f;
#pragma unroll
    for (int l=0; l<NL; l++) { e[l] = expf(lg[l]-mx); s += e[l]; }
    float inv = 1.f/s;
    int b = m >> 10, t = m & (NT-1);
    float* wp = &g_w[((b*NH + h)*NT + t)*NL];
#pragma unroll
    for (int l=0; l<NL; l++) wp[l] = e[l]*inv;
}

/* =====================================================================
 *  Attention (tf32 mma.sync), pair-balanced, 512 threads
 *  Q/K canonical [t][68], V natural [j][72] (no transpose),
 *  Ssm pk8 [128][136]; all main-loop fragment loads conflict-free.
 * ===================================================================== */
#define AQ_STR 68
#define AV_STR 72
#define AS_STR 136
#define A_QS (128*AQ_STR)
#define A_KS (128*AQ_STR)
#define A_VS (128*AV_STR)
#define A_SS (128*AS_STR)
#define A_WS (128*NL)
#define ATTN_SMEM ((A_QS + A_KS + A_VS + A_SS + A_WS + 128)*4)

__global__ void __launch_bounds__(512,1)
attn_tc()
{
    extern __shared__ float sm[];
    float* Qs  = sm;
    float* Ks  = Qs  + A_QS;
    float* Vs  = Ks  + A_KS;
    float* Ssm = Vs  + A_VS;
    float* Ws  = Ssm + A_SS;
    float* den = Ws  + A_WS;
    const uint32_t uQs = s2u(Qs), uKs = s2u(Ks), uVs = s2u(Vs), uWs = s2u(Ws);

    const int tid = threadIdx.x;
    const int wid = tid>>5, lane = tid&31, g = lane>>2, tg = lane&3;
    const int wm = wid>>2, wn = wid&3;
    const int bh = blockIdx.y;
    const int pid = blockIdx.x;

    const float* __restrict__ Qg = g_Qp + (size_t)bh*NT*HD;
    const float* __restrict__ Kg = g_Kp + (size_t)bh*NT*HD;
    const float* __restrict__ Vg = g_V  + (size_t)bh*NT*HD;
    const float* __restrict__ wg = g_w  + (size_t)bh*NT*NL;
    const int b = bh >> 4, h = bh & 15;

    for (int sel = 0; sel < 2; sel++) {
        const int qt = sel ? (7 - pid) : pid;
        const int i0 = qt*128;

        __syncthreads();   /* prior sel fully done with smem */

        /* async: Q tile + level weights */
#pragma unroll
        for (int r=0; r<4; r++) {
            int fid = r*512 + tid;
            int q = fid>>4, dq = (fid&15)<<2;
            cpa16(uQs + (q*AQ_STR + dq)*4, &Qg[(size_t)(i0+q)*HD + dq]);
        }
        if (tid < 384) cpa16(uWs + tid*16, &wg[i0*NL + tid*4]);
        if (tid < 128) den[tid] = 0.f;

        float oacc[2][2][4];
#pragma unroll
        for (int mt=0; mt<2; mt++)
#pragma unroll
            for (int nt=0; nt<2; nt++)
#pragma unroll
                for (int r=0; r<4; r++) oacc[mt][nt][r] = 0.f;

        const int ntiles = qt + 1;
        for (int jt = 0; jt < ntiles; jt++) {
            const int j0g = jt*128;
            __syncthreads();   /* prior O-phase done reading Ks/Vs */
#pragma unroll
            for (int r=0; r<4; r++) {
                int fid = r*512 + tid;
                int j = fid>>4, dq = (fid&15)<<2;
                cpa16(uKs + (j*AQ_STR + dq)*4, &Kg[(size_t)(j0g+j)*HD + dq]);
                cpa16(uVs + (j*AV_STR + dq)*4, &Vg[(size_t)(j0g+j)*HD + dq]);
            }
            cpa_commit();
            cpa_wait0();
            __syncthreads();

            /* ---- S = Q K^T : warp tile 32x32 ---- */
            float sacc[2][4][4];
#pragma unroll
            for (int mt=0; mt<2; mt++)
#pragma unroll
                for (int nt=0; nt<4; nt++)
#pragma unroll
                    for (int r=0; r<4; r++) sacc[mt][nt][r] = 0.f;

            const unsigned* Qu = (const unsigned*)Qs;
            const unsigned* Ku = (const unsigned*)Ks;
#pragma unroll
            for (int k8=0; k8<8; k8++) {
                unsigned a[2][4];
#pragma unroll
                for (int mt=0; mt<2; mt++) {
                    int rb = wm*32 + mt*16;
                    a[mt][0] = Qu[(rb+g  )*AQ_STR + k8*8 + tg];
                    a[mt][1] = Qu[(rb+g+8)*AQ_STR + k8*8 + tg];
                    a[mt][2] = Qu[(rb+g  )*AQ_STR + k8*8 + tg+4];
                    a[mt][3] = Qu[(rb+g+8)*AQ_STR + k8*8 + tg+4];
                }
#pragma unroll
                for (int nt=0; nt<4; nt++) {
                    int jr = wn*32 + nt*8 + g;
                    unsigned bfr[2];
                    bfr[0] = Ku[jr*AQ_STR + k8*8 + tg];
                    bfr[1] = Ku[jr*AQ_STR + k8*8 + tg+4];
                    mma8(sacc[0][nt], a[0], bfr);
                    mma8(sacc[1][nt], a[1], bfr);
                }
            }

            /* ---- weight + mask + store Ssm + row sums ---- */
            float rs[2][2] = {{0.f,0.f},{0.f,0.f}};
#pragma unroll
            for (int mt=0; mt<2; mt++) {
#pragma unroll
                for (int nt=0; nt<4; nt++) {
#pragma unroll
                    for (int r=0; r<4; r++) {
                        int il = wm*32 + mt*16 + g + ((r>>1)<<3);
                        int jl = wn*32 + nt*8 + 2*tg + (r&1);
                        int i = i0 + il, j = j0g + jl;
                        float v = 0.f;
                        if (j <= i) {
                            int lev = 31 - __clz(j ^ (i+1));
                            v = sacc[mt][nt][r] * Ws[il*NL + lev];
                        }
                        rs[mt][r>>1] += v;
                        Ssm[il*AS_STR + pk8(jl)] = __uint_as_float(f2tf(v));
                    }
                }
            }
#pragma unroll
            for (int mt=0; mt<2; mt++) {
#pragma unroll
                for (int hf=0; hf<2; hf++) {
                    float v = rs[mt][hf];
                    v += __shfl_xor_sync(0xFFFFFFFFu, v, 1);
                    v += __shfl_xor_sync(0xFFFFFFFFu, v, 2);
                    if (tg == 0)
                        atomicAdd(&den[wm*32 + mt*16 + g + hf*8], v);
                }
            }
            __syncthreads();

            /* ---- O += Ssm @ V : warp tile 32x16 ---- */
            const unsigned* Su = (const unsigned*)Ssm;
            const unsigned* Vu = (const unsigned*)Vs;
#pragma unroll
            for (int k8=0; k8<16; k8++) {
                unsigned a[2][4];
#pragma unroll
                for (int mt=0; mt<2; mt++) {
                    int rb = wm*32 + mt*16;
                    uint2 p0 = *(const uint2*)&Su[(rb+g  )*AS_STR + k8*8 + 2*tg];
                    uint2 p1 = *(const uint2*)&Su[(rb+g+8)*AS_STR + k8*8 + 2*tg];
                    a[mt][0]=p0.x; a[mt][2]=p0.y; a[mt][1]=p1.x; a[mt][3]=p1.y;
                }
#pragma unroll
                for (int nt=0; nt<2; nt++) {
                    int ec = wn*16 + nt*8 + g;
                    unsigned bfr[2];
                    bfr[0] = Vu[(k8*8+tg  )*AV_STR + ec];
                    bfr[1] = Vu[(k8*8+tg+4)*AV_STR + ec];
                    mma8(oacc[0][nt], a[0], bfr);
                    mma8(oacc[1][nt], a[1], bfr);
                }
            }
        }

        __syncthreads();   /* den atomics complete */

        float rcp[2][2];
#pragma unroll
        for (int mt=0; mt<2; mt++)
#pragma unroll
            for (int hf=0; hf<2; hf++)
                rcp[mt][hf] = 1.f / fmaxf(den[wm*32 + mt*16 + g + hf*8], 1e-6f);
#pragma unroll
        for (int mt=0; mt<2; mt++) {
#pragma unroll
            for (int nt=0; nt<2; nt++) {
#pragma unroll
                for (int r=0; r<4; r++) {
                    int il = wm*32 + mt*16 + g + ((r>>1)<<3);
                    int e  = wn*16 + nt*8 + 2*tg + (r&1);
                    g_attn[(size_t)(b*NT + i0 + il)*NHD + h*HD + e] =
                        __uint_as_float(f2tf(oacc[mt][nt][r] * rcp[mt][r>>1]));
                }
            }
        }
    }
}

/* ===================================================================== */
extern "C" void kernel_launch(void* const* d_in, const int* in_sizes, int n_in,
                              void* d_out, int out_size)
{
    const float* x  = (const float*)d_in[0];
    const float* qw = (const float*)d_in[1];
    const float* qb = (const float*)d_in[2];
    const float* kw = (const float*)d_in[3];
    const float* kb = (const float*)d_in[4];
    const float* vw = (const float*)d_in[5];
    const float* vb = (const float*)d_in[6];
    const float* lw = (const float*)d_in[7];
    const float* lb = (const float*)d_in[8];
    const float* ow = (const float*)d_in[9];
    const float* ob = (const float*)d_in[10];
    float* out = (float*)d_out;

    cudaFuncSetAttribute(gemm_tc, cudaFuncAttributeMaxDynamicSharedMemorySize, GEMM_SMEM);
    cudaFuncSetAttribute(attn_tc, cudaFuncAttributeMaxDynamicSharedMemorySize, ATTN_SMEM);

    cvt_kernel<<<CV5/256, 256>>>((const float4*)x, (const float4*)qw, (const float4*)kw,
                                 (const float4*)vw, (const float4*)lw, (const float4*)ow);
    gemm_tc<<<dim3(8,16,4), 512, GEMM_SMEM>>>(qb, kb, vb, lb, nullptr, NHD, MODE_Q);
    softmax_kernel<<<(NM*NH + 255)/256, 256>>>();
    attn_tc<<<dim3(4, NB*NH), 512, ATTN_SMEM>>>();
    gemm_tc<<<dim3(8,16,1), 512, GEMM_SMEM>>>(ob, ob, ob, ob, out, NHD, MODE_O);
}

// round 17
// speedup vs baseline: 4.0889x; 1.0323x over previous
#include <cuda_runtime.h>
#include <math.h>
#include <stdint.h>

#define NB 2
#define NT 1024
#define NH 16
#define HD 64
#define NL 12
#define NM (NB*NT)        /* 2048 */
#define NHL (NH*NL)       /* 192  */
#define NHD (NH*HD)       /* 1024 */

/* ---------------- scratch ---------------- */
__device__ float g_Qp[NB*NH*NT*HD];
__device__ float g_Kp[NB*NH*NT*HD];
__device__ float g_V [NB*NH*NT*HD];
__device__ float g_logits[NM*NHL];
__device__ float g_w[NB*NH*NT*NL];
__device__ float g_attn[NM*NHD];
/* tf32 pre-rounded inputs */
__device__ float g_xT [NM*1024];
__device__ float g_qwT[1024*NHD];
__device__ float g_kwT[1024*NHD];
__device__ float g_vwT[1024*NHD];
__device__ float g_lwT[1024*NHL];
__device__ float g_owT[NHD*1024];

/* ---------------- helpers ---------------- */
__device__ __forceinline__ unsigned f2tf(float f){
    unsigned u; asm("cvt.rna.tf32.f32 %0, %1;" : "=r"(u) : "f"(f)); return u;
}
__device__ __forceinline__ void mma8(float* c, const unsigned* a, const unsigned* b){
    asm volatile("mma.sync.aligned.m16n8k8.row.col.f32.tf32.tf32.f32 "
        "{%0,%1,%2,%3}, {%4,%5,%6,%7}, {%8,%9}, {%0,%1,%2,%3};"
        : "+f"(c[0]),"+f"(c[1]),"+f"(c[2]),"+f"(c[3])
        : "r"(a[0]),"r"(a[1]),"r"(a[2]),"r"(a[3]),"r"(b[0]),"r"(b[1]));
}
__device__ __forceinline__ int pk8(int c){ return (c & ~7) | ((c&3)<<1) | ((c>>2)&1); }
__device__ __forceinline__ uint32_t s2u(const void* p){
    uint32_t a;
    asm("{ .reg .u64 t; cvta.to.shared.u64 t, %1; cvt.u32.u64 %0, t; }" : "=r"(a) : "l"(p));
    return a;
}
__device__ __forceinline__ void cpa16(uint32_t dst, const void* src){
    asm volatile("cp.async.cg.shared.global [%0], [%1], 16;" :: "r"(dst), "l"(src) : "memory");
}
__device__ __forceinline__ void cpa_commit(){
    asm volatile("cp.async.commit_group;" ::: "memory");
}
__device__ __forceinline__ void cpa_wait0(){
    asm volatile("cp.async.wait_group 0;" ::: "memory");
}
__device__ __forceinline__ void cpa_wait1(){
    asm volatile("cp.async.wait_group 1;" ::: "memory");
}

enum { MODE_Q = 0, MODE_K = 1, MODE_V = 2, MODE_L = 3, MODE_O = 4 };

/* =====================================================================
 *  Prepass: round inputs to tf32 (float4 pass)
 * ===================================================================== */
#define CV0 524288
#define CV1 786432
#define CV2 1048576
#define CV3 1310720
#define CV4 1359872
#define CV5 1622016
__global__ void cvt_kernel(const float4* __restrict__ x,  const float4* __restrict__ qw,
                           const float4* __restrict__ kw, const float4* __restrict__ vw,
                           const float4* __restrict__ lw, const float4* __restrict__ ow)
{
    int id = blockIdx.x*blockDim.x + threadIdx.x;
    const float4* s; float4* d; int off;
    if      (id < CV0) { s=x;  d=(float4*)g_xT;  off=id; }
    else if (id < CV1) { s=qw; d=(float4*)g_qwT; off=id-CV0; }
    else if (id < CV2) { s=kw; d=(float4*)g_kwT; off=id-CV1; }
    else if (id < CV3) { s=vw; d=(float4*)g_vwT; off=id-CV2; }
    else if (id < CV4) { s=lw; d=(float4*)g_lwT; off=id-CV3; }
    else if (id < CV5) { s=ow; d=(float4*)g_owT; off=id-CV4; }
    else return;
    float4 v = s[off];
    v.x = __uint_as_float(f2tf(v.x));
    v.y = __uint_as_float(f2tf(v.y));
    v.z = __uint_as_float(f2tf(v.z));
    v.w = __uint_as_float(f2tf(v.w));
    d[off] = v;
}

/* =====================================================================
 *  tf32 mma.sync GEMM, cp.async 3-stage, K-chunk 64
 *  C[2048,N] = A[2048,1024] @ W[1024,N] + bias
 *  A stage: [128 m][68]  (LDS.32 frags CF)
 *  B stage: [64 k][136]  (LDS.32 frags CF)
 * ===================================================================== */
#define GA_STR 68
#define GB_STR 136
#define GA_BYTES (128*GA_STR*4)     /* 34816 */
#define GB_BYTES (64*GB_STR*4)      /* 34816 */
#define GSTAGE   (GA_BYTES + GB_BYTES)
#define GEMM_SMEM (3*GSTAGE)        /* 208896 */

__global__ void __launch_bounds__(512,1)
gemm_tc(const float* __restrict__ Bi0, const float* __restrict__ Bi1,
        const float* __restrict__ Bi2, const float* __restrict__ Bi3,
        float* __restrict__ outp, int Npar, int mode0)
{
    extern __shared__ float sm[];
    const uint32_t sb = s2u(sm);

    const int z = blockIdx.z;
    const int mode = mode0 + z;
    const int N = (mode == MODE_L) ? NHL : Npar;
    const int n0 = blockIdx.x*128;
    if (n0 >= N) return;
    const int m0 = blockIdx.y*128;
    const float* __restrict__ bias = (z==0)?Bi0:(z==1)?Bi1:(z==2)?Bi2:Bi3;
    const float* __restrict__ W =
        (mode==MODE_Q)?g_qwT:(mode==MODE_K)?g_kwT:(mode==MODE_V)?g_vwT:
        (mode==MODE_L)?g_lwT:g_owT;
    const float* __restrict__ A = (mode==MODE_O) ? g_attn : g_xT;

    const int tid = threadIdx.x;
    const int wid = tid>>5, lane = tid&31, g = lane>>2, tg = lane&3;
    const int wm = wid>>2, wn = wid&3;

    float acc[2][4][4];
#pragma unroll
    for (int mt=0; mt<2; mt++)
#pragma unroll
        for (int nt=0; nt<4; nt++)
#pragma unroll
            for (int r=0; r<4; r++) acc[mt][nt][r] = 0.f;

    /* producer: chunk c (64 k) -> stage st */
    auto produce = [&](int c, int st){
        const int k0c = c*64;
        const uint32_t base = sb + st*GSTAGE;
#pragma unroll
        for (int p=0; p<4; p++) {
            int fid = p*512 + tid;
            int m = fid>>4, k4 = (fid&15)<<2;
            cpa16(base + (m*GA_STR + k4)*4, &A[(size_t)(m0+m)*1024 + k0c + k4]);
        }
#pragma unroll
        for (int p=0; p<4; p++) {
            int fid = p*512 + tid;
            int k = fid>>5, n4 = (fid&31)<<2;
            uint32_t dst = base + GA_BYTES + (k*GB_STR + n4)*4;
            if (n0 + n4 + 3 < N) {
                cpa16(dst, &W[(size_t)(k0c+k)*N + n0 + n4]);
            } else {
                float4 zz = {0.f,0.f,0.f,0.f};
                *(float4*)((char*)sm + (dst - sb)) = zz;
            }
        }
        cpa_commit();
    };

    produce(0, 0);
    produce(1, 1);

    for (int c = 0; c < 16; c++) {
        const int st = c % 3;
        if (c < 15) cpa_wait1(); else cpa_wait0();
        __syncthreads();
        if (c + 2 < 16) produce(c+2, (c+2)%3);

        const unsigned* Au = (const unsigned*)(sm + st*(GSTAGE/4));
        const unsigned* Bu = Au + GA_BYTES/4;
#pragma unroll
        for (int k8 = 0; k8 < 8; k8++) {
            unsigned a[2][4];
#pragma unroll
            for (int mt=0; mt<2; mt++) {
                int rb = wm*32 + mt*16;
                a[mt][0] = Au[(rb+g  )*GA_STR + k8*8 + tg];
                a[mt][1] = Au[(rb+g+8)*GA_STR + k8*8 + tg];
                a[mt][2] = Au[(rb+g  )*GA_STR + k8*8 + tg+4];
                a[mt][3] = Au[(rb+g+8)*GA_STR + k8*8 + tg+4];
            }
#pragma unroll
            for (int nt=0; nt<4; nt++) {
                int nc = wn*32 + nt*8 + g;
                unsigned b[2];
                b[0] = Bu[(k8*8+tg  )*GB_STR + nc];
                b[1] = Bu[(k8*8+tg+4)*GB_STR + nc];
                mma8(acc[0][nt], a[0], b);
                mma8(acc[1][nt], a[1], b);
            }
        }
    }

    /* epilogue */
#pragma unroll
    for (int mt=0; mt<2; mt++) {
#pragma unroll
        for (int nt=0; nt<4; nt++) {
#pragma unroll
            for (int r=0; r<4; r++) {
                int m = m0 + wm*32 + mt*16 + g + ((r>>1)<<3);
                int n = n0 + wn*32 + nt*8 + 2*tg + (r&1);
                if (n >= N) continue;
                float c = acc[mt][nt][r] + bias[n];
                if (mode == MODE_Q || mode == MODE_K) {
                    float p = (c > 0.f) ? (c + 1.f) : expf(c);
                    int b = m >> 10, t = m & (NT-1);
                    int h = n >> 6,  d = n & 63;
                    float* dst = (mode == MODE_Q) ? g_Qp : g_Kp;
                    dst[((b*NH + h)*NT + t)*HD + d] = __uint_as_float(f2tf(p));
                } else if (mode == MODE_V) {
                    int b = m >> 10, t = m & (NT-1);
                    int h = n >> 6,  d = n & 63;
                    g_V[((b*NH + h)*NT + t)*HD + d] = __uint_as_float(f2tf(c));
                } else if (mode == MODE_L) {
                    g_logits[m*NHL + n] = c;
                } else {
                    outp[m*NHD + n] = c;
                }
            }
        }
    }
}

/* =====================================================================
 *  Softmax over L=12 per (b,h,t)
 * ===================================================================== */
__global__ void softmax_kernel()
{
    int id = blockIdx.x*blockDim.x + threadIdx.x;
    if (id >= NM*NH) return;
    int m = id / NH, h = id % NH;
    const float* lg = &g_logits[m*NHL + h*NL];
    float mx = lg[0];
#pragma unroll
    for (int l=1; l<NL; l++) mx = fmaxf(mx, lg[l]);
    float e[NL], s = 0.f;
#pragma unroll
    for (int l=0; l<NL; l++) { e[l] = expf(lg[l]-mx); s += e[l]; }
    float inv = 1.f/s;
    int b = m >> 10, t = m & (NT-1);
    float* wp = &g_w[((b*NH + h)*NT + t)*NL];
#pragma unroll
    for (int l=0; l<NL; l++) wp[l] = e[l]*inv;
}

/* =====================================================================
 *  Attention (tf32 mma.sync), pair-balanced, prefetch-reordered:
 *  K(jt+1) issued after weight-sync (hidden behind O-phase),
 *  V(jt+1) issued after O-sync.
 * ===================================================================== */
#define AQ_STR 68
#define AV_STR 72
#define AS_STR 136
#define A_QS (128*AQ_STR)
#define A_KS (128*AQ_STR)
#define A_VS (128*AV_STR)
#define A_SS (128*AS_STR)
#define A_WS (128*NL)
#define ATTN_SMEM ((A_QS + A_KS + A_VS + A_SS + A_WS + 128)*4)

__global__ void __launch_bounds__(512,1)
attn_tc()
{
    extern __shared__ float sm[];
    float* Qs  = sm;
    float* Ks  = Qs  + A_QS;
    float* Vs  = Ks  + A_KS;
    float* Ssm = Vs  + A_VS;
    float* Ws  = Ssm + A_SS;
    float* den = Ws  + A_WS;
    const uint32_t uQs = s2u(Qs), uKs = s2u(Ks), uVs = s2u(Vs), uWs = s2u(Ws);

    const int tid = threadIdx.x;
    const int wid = tid>>5, lane = tid&31, g = lane>>2, tg = lane&3;
    const int wm = wid>>2, wn = wid&3;
    const int bh = blockIdx.y;
    const int pid = blockIdx.x;

    const float* __restrict__ Qg = g_Qp + (size_t)bh*NT*HD;
    const float* __restrict__ Kg = g_Kp + (size_t)bh*NT*HD;
    const float* __restrict__ Vg = g_V  + (size_t)bh*NT*HD;
    const float* __restrict__ wg = g_w  + (size_t)bh*NT*NL;
    const int b = bh >> 4, h = bh & 15;

    /* 128 rows x 64 floats = 2048 x 16B per tile */
    auto loadK = [&](int jt){
#pragma unroll
        for (int r=0; r<4; r++) {
            int fid = r*512 + tid;
            int j = fid>>4, dq = (fid&15)<<2;
            cpa16(uKs + (j*AQ_STR + dq)*4, &Kg[(size_t)(jt*128+j)*HD + dq]);
        }
    };
    auto loadV = [&](int jt){
#pragma unroll
        for (int r=0; r<4; r++) {
            int fid = r*512 + tid;
            int j = fid>>4, dq = (fid&15)<<2;
            cpa16(uVs + (j*AV_STR + dq)*4, &Vg[(size_t)(jt*128+j)*HD + dq]);
        }
    };

    for (int sel = 0; sel < 2; sel++) {
        const int qt = sel ? (7 - pid) : pid;
        const int i0 = qt*128;

        __syncthreads();   /* prior sel fully done with smem */

        /* async: Q tile + level weights + K(0),V(0) */
#pragma unroll
        for (int r=0; r<4; r++) {
            int fid = r*512 + tid;
            int q = fid>>4, dq = (fid&15)<<2;
            cpa16(uQs + (q*AQ_STR + dq)*4, &Qg[(size_t)(i0+q)*HD + dq]);
        }
        if (tid < 384) cpa16(uWs + tid*16, &wg[i0*NL + tid*4]);
        if (tid < 128) den[tid] = 0.f;
        loadK(0);
        loadV(0);
        cpa_commit();
        cpa_wait0();
        __syncthreads();

        float oacc[2][2][4];
#pragma unroll
        for (int mt=0; mt<2; mt++)
#pragma unroll
            for (int nt=0; nt<2; nt++)
#pragma unroll
                for (int r=0; r<4; r++) oacc[mt][nt][r] = 0.f;

        const int ntiles = qt + 1;
        for (int jt = 0; jt < ntiles; jt++) {
            const int j0g = jt*128;

            /* ---- S = Q K^T : warp tile 32x32 ---- */
            float sacc[2][4][4];
#pragma unroll
            for (int mt=0; mt<2; mt++)
#pragma unroll
                for (int nt=0; nt<4; nt++)
#pragma unroll
                    for (int r=0; r<4; r++) sacc[mt][nt][r] = 0.f;

            const unsigned* Qu = (const unsigned*)Qs;
            const unsigned* Ku = (const unsigned*)Ks;
#pragma unroll
            for (int k8=0; k8<8; k8++) {
                unsigned a[2][4];
#pragma unroll
                for (int mt=0; mt<2; mt++) {
                    int rb = wm*32 + mt*16;
                    a[mt][0] = Qu[(rb+g  )*AQ_STR + k8*8 + tg];
                    a[mt][1] = Qu[(rb+g+8)*AQ_STR + k8*8 + tg];
                    a[mt][2] = Qu[(rb+g  )*AQ_STR + k8*8 + tg+4];
                    a[mt][3] = Qu[(rb+g+8)*AQ_STR + k8*8 + tg+4];
                }
#pragma unroll
                for (int nt=0; nt<4; nt++) {
                    int jr = wn*32 + nt*8 + g;
                    unsigned bfr[2];
                    bfr[0] = Ku[jr*AQ_STR + k8*8 + tg];
                    bfr[1] = Ku[jr*AQ_STR + k8*8 + tg+4];
                    mma8(sacc[0][nt], a[0], bfr);
                    mma8(sacc[1][nt], a[1], bfr);
                }
            }

            /* ---- weight + mask + store Ssm + row sums ---- */
            float rs[2][2] = {{0.f,0.f},{0.f,0.f}};
#pragma unroll
            for (int mt=0; mt<2; mt++) {
#pragma unroll
                for (int nt=0; nt<4; nt++) {
#pragma unroll
                    for (int r=0; r<4; r++) {
                        int il = wm*32 + mt*16 + g + ((r>>1)<<3);
                        int jl = wn*32 + nt*8 + 2*tg + (r&1);
                        int i = i0 + il, j = j0g + jl;
                        float v = 0.f;
                        if (j <= i) {
                            int lev = 31 - __clz(j ^ (i+1));
                            v = sacc[mt][nt][r] * Ws[il*NL + lev];
                        }
                        rs[mt][r>>1] += v;
                        Ssm[il*AS_STR + pk8(jl)] = __uint_as_float(f2tf(v));
                    }
                }
            }
#pragma unroll
            for (int mt=0; mt<2; mt++) {
#pragma unroll
                for (int hf=0; hf<2; hf++) {
                    float v = rs[mt][hf];
                    v += __shfl_xor_sync(0xFFFFFFFFu, v, 1);
                    v += __shfl_xor_sync(0xFFFFFFFFu, v, 2);
                    if (tg == 0)
                        atomicAdd(&den[wm*32 + mt*16 + g + hf*8], v);
                }
            }
            __syncthreads();           /* Ssm visible, K consumed by all */

            /* prefetch next K behind O-phase */
            if (jt + 1 < ntiles) { loadK(jt+1); cpa_commit(); }

            /* ---- O += Ssm @ V : warp tile 32x16 ---- */
            const unsigned* Su = (const unsigned*)Ssm;
            const unsigned* Vu = (const unsigned*)Vs;
#pragma unroll
            for (int k8=0; k8<16; k8++) {
                unsigned a[2][4];
#pragma unroll
                for (int mt=0; mt<2; mt++) {
                    int rb = wm*32 + mt*16;
                    uint2 p0 = *(const uint2*)&Su[(rb+g  )*AS_STR + k8*8 + 2*tg];
                    uint2 p1 = *(const uint2*)&Su[(rb+g+8)*AS_STR + k8*8 + 2*tg];
                    a[mt][0]=p0.x; a[mt][2]=p0.y; a[mt][1]=p1.x; a[mt][3]=p1.y;
                }
#pragma unroll
                for (int nt=0; nt<2; nt++) {
                    int ec = wn*16 + nt*8 + g;
                    unsigned bfr[2];
                    bfr[0] = Vu[(k8*8+tg  )*AV_STR + ec];
                    bfr[1] = Vu[(k8*8+tg+4)*AV_STR + ec];
                    mma8(oacc[0][nt], a[0], bfr);
                    mma8(oacc[1][nt], a[1], bfr);
                }
            }
            __syncthreads();           /* V + Ssm consumed by all */

            if (jt + 1 < ntiles) {
                loadV(jt+1); cpa_commit();
                cpa_wait0();           /* K + V groups done */
                __syncthreads();
            }
        }

        float rcp[2][2];
#pragma unroll
        for (int mt=0; mt<2; mt++)
#pragma unroll
            for (int hf=0; hf<2; hf++)
                rcp[mt][hf] = 1.f / fmaxf(den[wm*32 + mt*16 + g + hf*8], 1e-6f);
#pragma unroll
        for (int mt=0; mt<2; mt++) {
#pragma unroll
            for (int nt=0; nt<2; nt++) {
#pragma unroll
                for (int r=0; r<4; r++) {
                    int il = wm*32 + mt*16 + g + ((r>>1)<<3);
                    int e  = wn*16 + nt*8 + 2*tg + (r&1);
                    g_attn[(size_t)(b*NT + i0 + il)*NHD + h*HD + e] =
                        __uint_as_float(f2tf(oacc[mt][nt][r] * rcp[mt][r>>1]));
                }
            }
        }
    }
}

/* ===================================================================== */
extern "C" void kernel_launch(void* const* d_in, const int* in_sizes, int n_in,
                              void* d_out, int out_size)
{
    const float* x  = (const float*)d_in[0];
    const float* qw = (const float*)d_in[1];
    const float* qb = (const float*)d_in[2];
    const float* kw = (const float*)d_in[3];
    const float* kb = (const float*)d_in[4];
    const float* vw = (const float*)d_in[5];
    const float* vb = (const float*)d_in[6];
    const float* lw = (const float*)d_in[7];
    const float* lb = (const float*)d_in[8];
    const float* ow = (const float*)d_in[9];
    const float* ob = (const float*)d_in[10];
    float* out = (float*)d_out;

    cudaFuncSetAttribute(gemm_tc, cudaFuncAttributeMaxDynamicSharedMemorySize, GEMM_SMEM);
    cudaFuncSetAttribute(attn_tc, cudaFuncAttributeMaxDynamicSharedMemorySize, ATTN_SMEM);

    cvt_kernel<<<CV5/256, 256>>>((const float4*)x, (const float4*)qw, (const float4*)kw,
                                 (const float4*)vw, (const float4*)lw, (const float4*)ow);
    gemm_tc<<<dim3(8,16,4), 512, GEMM_SMEM>>>(qb, kb, vb, lb, nullptr, NHD, MODE_Q);
    softmax_kernel<<<(NM*NH + 255)/256, 256>>>();
    attn_tc<<<dim3(4, NB*NH), 512, ATTN_SMEM>>>();
    gemm_tc<<<dim3(8,16,1), 512, GEMM_SMEM>>>(ob, ob, ob, ob, out, NHD, MODE_O);
}